// round 10
// baseline (speedup 1.0000x reference)
#include <cuda_runtime.h>
#include <cuda_bf16.h>
#include <cstdint>

// Problem constants
#define SEQ     2048
#define BATCH   2
#define HIDDEN  2048
#define NHEADS  16
#define HDIM    128
#define M_ROWS  (SEQ * BATCH)       // 4096
#define QKV_N   (3 * HIDDEN)        // 6144

// ---------------------------------------------------------------------------
// Scratch (device globals: allocation-free per harness rules)
// ---------------------------------------------------------------------------
__device__ __nv_bfloat16 g_Ahi[(size_t)M_ROWS * HIDDEN];
__device__ __nv_bfloat16 g_Alo[(size_t)M_ROWS * HIDDEN];
__device__ __nv_bfloat16 g_Bqkv_hi[(size_t)QKV_N * HIDDEN];
__device__ __nv_bfloat16 g_Bqkv_lo[(size_t)QKV_N * HIDDEN];
__device__ __nv_bfloat16 g_Bd_hi[(size_t)HIDDEN * HIDDEN];
__device__ __nv_bfloat16 g_Bd_lo[(size_t)HIDDEN * HIDDEN];
#define HSZ ((size_t)32 * SEQ * HDIM)
__device__ __nv_bfloat16 g_Qh[HSZ];
__device__ __nv_bfloat16 g_Ql[HSZ];
__device__ __nv_bfloat16 g_Kh[HSZ];
__device__ __nv_bfloat16 g_Kl[HSZ];
__device__ __nv_bfloat16 g_Vh[HSZ];
__device__ __nv_bfloat16 g_Vl[HSZ];

// ---------------------------------------------------------------------------
// Helpers
// ---------------------------------------------------------------------------
__device__ __forceinline__ uint32_t smem_to_u32(const void* p) {
    uint32_t a;
    asm("{ .reg .u64 t; cvta.to.shared.u64 t, %1; cvt.u32.u64 %0, t; }" : "=r"(a) : "l"(p));
    return a;
}
__device__ __forceinline__ void cp16(uint32_t s, const void* g) {
    asm volatile("cp.async.cg.shared.global [%0], [%1], 16;" :: "r"(s), "l"(g));
}
#define CP_COMMIT() asm volatile("cp.async.commit_group;" ::: "memory")
#define CP_WAIT(n)  asm volatile("cp.async.wait_group %0;" :: "n"(n) : "memory")

#define MMA16816(d, a, b) \
    asm volatile("mma.sync.aligned.m16n8k16.row.col.f32.bf16.bf16.f32 " \
        "{%0,%1,%2,%3}, {%4,%5,%6,%7}, {%8,%9}, {%0,%1,%2,%3};" \
        : "+f"((d)[0]), "+f"((d)[1]), "+f"((d)[2]), "+f"((d)[3]) \
        : "r"((a)[0]), "r"((a)[1]), "r"((a)[2]), "r"((a)[3]), \
          "r"((b)[0]), "r"((b)[1]))

#define LDSM4(r, addr) \
    asm volatile("ldmatrix.sync.aligned.m8n8.x4.shared.b16 {%0,%1,%2,%3}, [%4];" \
        : "=r"((r)[0]), "=r"((r)[1]), "=r"((r)[2]), "=r"((r)[3]) : "r"(addr))
#define LDSM4T(r, addr) \
    asm volatile("ldmatrix.sync.aligned.m8n8.x4.trans.shared.b16 {%0,%1,%2,%3}, [%4];" \
        : "=r"((r)[0]), "=r"((r)[1]), "=r"((r)[2]), "=r"((r)[3]) : "r"(addr))

__device__ __forceinline__ uint32_t bf2pack(float a, float b) {
    __nv_bfloat162 t = __floats2bfloat162_rn(a, b);
    return *(uint32_t*)&t;
}
__device__ __forceinline__ float bf16res(float x) {
    return x - __bfloat162float(__float2bfloat16(x));
}
__device__ __forceinline__ __nv_bfloat162 split_hi2(float a, float b) {
    return __nv_bfloat162(__float2bfloat16(a), __float2bfloat16(b));
}
__device__ __forceinline__ __nv_bfloat162 split_lo2(float a, float b) {
    return __nv_bfloat162(__float2bfloat16(bf16res(a)), __float2bfloat16(bf16res(b)));
}

// ---------------------------------------------------------------------------
// Conversion kernels
// ---------------------------------------------------------------------------
__global__ void split_rm_kernel(const float* __restrict__ in,
                                __nv_bfloat16* __restrict__ hi,
                                __nv_bfloat16* __restrict__ lo, int n4)
{
    int i = blockIdx.x * blockDim.x + threadIdx.x;
    if (i >= n4) return;
    float4 v = ((const float4*)in)[i];
    ((__nv_bfloat162*)hi)[2 * i]     = split_hi2(v.x, v.y);
    ((__nv_bfloat162*)hi)[2 * i + 1] = split_hi2(v.z, v.w);
    ((__nv_bfloat162*)lo)[2 * i]     = split_lo2(v.x, v.y);
    ((__nv_bfloat162*)lo)[2 * i + 1] = split_lo2(v.z, v.w);
}

__global__ void split_tr_kernel(const float* __restrict__ in,
                                __nv_bfloat16* __restrict__ hi,
                                __nv_bfloat16* __restrict__ lo, int K, int N)
{
    __shared__ float t[32][33];
    const int n0 = blockIdx.x * 32, k0 = blockIdx.y * 32;
    const int tx = threadIdx.x, ty = threadIdx.y;
    #pragma unroll
    for (int i = 0; i < 4; i++)
        t[ty + 8 * i][tx] = in[(size_t)(k0 + ty + 8 * i) * N + n0 + tx];
    __syncthreads();
    #pragma unroll
    for (int i = 0; i < 4; i++) {
        const int r = ty + 8 * i;
        const float x = t[tx][r];
        __nv_bfloat16 h = __float2bfloat16(x);
        __nv_bfloat16 l = __float2bfloat16(x - __bfloat162float(h));
        const size_t o = (size_t)(n0 + r) * K + k0 + tx;
        hi[o] = h; lo[o] = l;
    }
}

// ---------------------------------------------------------------------------
// bf16x3 mma.sync GEMM, 128x256 CTA tile, 512 threads (16 warps, 4x4),
// BK=32, 3-stage cp.async pipeline, ldmatrix fragments.
// C[M,N] = A[M,K] @ B^T (B stored [N,K]); D = AhBh + AhBl + AlBh.
// out_mode 0: fp32 C (+bias). out_mode 1: QKV split epilogue.
// ---------------------------------------------------------------------------
#define GBK 32
#define LDS_STRIDE 40
#define A_MAT (128 * LDS_STRIDE * 2)          // 10240 B
#define B_MAT (256 * LDS_STRIDE * 2)          // 20480 B
#define STAGE_BYTES (2 * A_MAT + 2 * B_MAT)   // 61440 B  (Ah, Al, Bh, Bl)
#define OFF_AH 0
#define OFF_AL A_MAT
#define OFF_BH (2 * A_MAT)
#define OFF_BL (2 * A_MAT + B_MAT)
#define NSTAGE 3
#define GEMM_SMEM (NSTAGE * STAGE_BYTES)      // 184320 B, 1 CTA/SM

__global__ __launch_bounds__(512, 1) void gemm_bf16x3_mma_kernel(
    const __nv_bfloat16* __restrict__ Ahi, const __nv_bfloat16* __restrict__ Alo,
    const __nv_bfloat16* __restrict__ Bhi, const __nv_bfloat16* __restrict__ Blo,
    const float* __restrict__ bias, float* __restrict__ C,
    int M, int N, int K, int out_mode)
{
    extern __shared__ char smem[];
    const uint32_t sbase = smem_to_u32(smem);
    const int tid  = threadIdx.x;
    const int wid  = tid >> 5;
    const int lane = tid & 31;
    const int g    = lane >> 2;
    const int tq   = lane & 3;
    const int wm   = wid & 3;            // 4 m-warps * 32 rows
    const int wn   = wid >> 2;           // 4 n-warps * 64 cols
    const int row0 = blockIdx.y * 128;
    const int col0 = blockIdx.x * 256;
    const int NC   = K / GBK;

    const int l_row = tid >> 2;          // 0..127
    const int l_kc  = (tid & 3) * 8;

    float acc[2][8][4];
    #pragma unroll
    for (int mt = 0; mt < 2; mt++)
        #pragma unroll
        for (int nt = 0; nt < 8; nt++)
            #pragma unroll
            for (int q = 0; q < 4; q++) acc[mt][nt][q] = 0.0f;

    auto load_stage = [&](int st, int kc) {
        const int kel = kc * GBK;
        const uint32_t stb = sbase + (uint32_t)st * STAGE_BYTES;
        // A: 128 rows, one cp16 per thread per matrix
        {
            const uint32_t soff = (uint32_t)(l_row * LDS_STRIDE + l_kc) * 2;
            const size_t ga = (size_t)(row0 + l_row) * K + kel + l_kc;
            cp16(stb + OFF_AH + soff, Ahi + ga);
            cp16(stb + OFF_AL + soff, Alo + ga);
        }
        // B: 256 rows, two cp16 per thread per matrix
        #pragma unroll
        for (int i = 0; i < 2; i++) {
            const int row = l_row + i * 128;
            const uint32_t soff = (uint32_t)(row * LDS_STRIDE + l_kc) * 2;
            const size_t gb = (size_t)(col0 + row) * K + kel + l_kc;
            cp16(stb + OFF_BH + soff, Bhi + gb);
            cp16(stb + OFF_BL + soff, Blo + gb);
        }
        CP_COMMIT();
    };

    load_stage(0, 0);
    load_stage(1, 1);

    const int a_r = wm * 32 + (lane & 15);
    const int a_c = (lane >> 4) << 3;
    const int b_r = wn * 64 + (lane & 7) + (((lane >> 4) & 1) << 3);
    const int b_c = ((lane >> 3) & 1) << 3;

    for (int kc = 0; kc < NC; kc++) {
        const int st = kc % NSTAGE;
        if (kc + 2 < NC) load_stage((kc + 2) % NSTAGE, kc + 2);
        else             CP_COMMIT();       // keep group count uniform
        CP_WAIT(2);
        __syncthreads();

        const uint32_t stb = sbase + (uint32_t)st * STAGE_BYTES;

        #pragma unroll
        for (int ks = 0; ks < GBK; ks += 16) {
            uint32_t ah[2][4], al[2][4];
            #pragma unroll
            for (int mt = 0; mt < 2; mt++) {
                const uint32_t aa = stb + (uint32_t)(((a_r + mt * 16) * LDS_STRIDE) + ks + a_c) * 2;
                LDSM4(ah[mt], aa + OFF_AH);
                LDSM4(al[mt], aa + OFF_AL);
            }
            #pragma unroll
            for (int np = 0; np < 4; np++) {
                uint32_t bh[4], bl[4];
                const uint32_t ba = stb
                    + (uint32_t)(((b_r + np * 16) * LDS_STRIDE) + ks + b_c) * 2;
                LDSM4(bh, ba + OFF_BH);
                LDSM4(bl, ba + OFF_BL);
                #pragma unroll
                for (int half = 0; half < 2; half++) {
                    const int nt = 2 * np + half;
                    #pragma unroll
                    for (int mt = 0; mt < 2; mt++) {
                        MMA16816(acc[mt][nt], ah[mt], &bh[half * 2]);
                        MMA16816(acc[mt][nt], ah[mt], &bl[half * 2]);
                        MMA16816(acc[mt][nt], al[mt], &bh[half * 2]);
                    }
                }
            }
        }
        __syncthreads();
    }

    if (out_mode == 0) {
        #pragma unroll
        for (int mt = 0; mt < 2; mt++) {
            const int r1 = row0 + wm * 32 + mt * 16 + g;
            const int r2 = r1 + 8;
            #pragma unroll
            for (int nt = 0; nt < 8; nt++) {
                const int c = col0 + wn * 64 + nt * 8 + tq * 2;
                float2 o1 = make_float2(acc[mt][nt][0], acc[mt][nt][1]);
                float2 o2 = make_float2(acc[mt][nt][2], acc[mt][nt][3]);
                if (bias) {
                    const float b0 = bias[c], b1 = bias[c + 1];
                    o1.x += b0; o1.y += b1;
                    o2.x += b0; o2.y += b1;
                }
                *(float2*)(C + (size_t)r1 * N + c) = o1;
                *(float2*)(C + (size_t)r2 * N + c) = o2;
            }
        }
    } else {
        const float qs = 0.08838834764831845f;
        #pragma unroll
        for (int mt = 0; mt < 2; mt++) {
            const int r1 = row0 + wm * 32 + mt * 16 + g;
            const int r2 = r1 + 8;
            const int s1 = r1 >> 1, b1 = r1 & 1;
            const int s2 = r2 >> 1, b2 = r2 & 1;
            #pragma unroll
            for (int nt = 0; nt < 8; nt++) {
                const int c = col0 + wn * 64 + nt * 8 + tq * 2;
                const int h = c / 384;
                const int rem = c - h * 384;
                const int m = rem >> 7;
                const int d = rem & 127;
                float v10 = acc[mt][nt][0] + bias[c];
                float v11 = acc[mt][nt][1] + bias[c + 1];
                float v20 = acc[mt][nt][2] + bias[c];
                float v21 = acc[mt][nt][3] + bias[c + 1];
                if (m == 0) { v10 *= qs; v11 *= qs; v20 *= qs; v21 *= qs; }
                __nv_bfloat16* hi = (m == 0) ? g_Qh : (m == 1) ? g_Kh : g_Vh;
                __nv_bfloat16* lo = (m == 0) ? g_Ql : (m == 1) ? g_Kl : g_Vl;
                const size_t o1 = ((size_t)(b1 * 16 + h) * SEQ + s1) * HDIM + d;
                const size_t o2 = ((size_t)(b2 * 16 + h) * SEQ + s2) * HDIM + d;
                *(__nv_bfloat162*)(hi + o1) = split_hi2(v10, v11);
                *(__nv_bfloat162*)(lo + o1) = split_lo2(v10, v11);
                *(__nv_bfloat162*)(hi + o2) = split_hi2(v20, v21);
                *(__nv_bfloat162*)(lo + o2) = split_lo2(v20, v21);
            }
        }
    }
}

// ---------------------------------------------------------------------------
// Flash attention, bf16x3 mma.sync, causal (unchanged from R8).
// ---------------------------------------------------------------------------
#define AST 136
#define Q_BYTES (128 * AST * 2)
#define KV_MAT (64 * AST * 2)
#define KV_STAGE (4 * KV_MAT)
#define ATTN_SMEM (2 * Q_BYTES + 2 * KV_STAGE)

__global__ __launch_bounds__(256) void attn_mma_kernel()
{
    extern __shared__ char smem[];
    const uint32_t sb = smem_to_u32(smem);
    const int tid  = threadIdx.x;
    const int lane = tid & 31;
    const int w    = tid >> 5;
    const int g    = lane >> 2;
    const int tq   = lane & 3;
    const int bh   = blockIdx.y;
    const int b    = bh >> 4;
    const int h    = bh & 15;
    const size_t head_base = (size_t)bh * SEQ * HDIM;

    const int qa_r = w * 16 + (lane & 15);
    const int qa_c = (lane >> 4) << 3;
    const int kb_r = (lane & 7) + (((lane >> 4) & 1) << 3);
    const int kb_c = ((lane >> 3) & 1) << 3;
    const int vt_r = lane & 15;
    const int vt_c = (lane >> 4) << 3;

    for (int pass = 0; pass < 2; pass++) {
        const int qt = pass ? (15 - (int)blockIdx.x) : (int)blockIdx.x;
        const int qbase = qt * 128;
        const int ntiles = 2 * qt + 2;

        #pragma unroll
        for (int i = 0; i < 8; i++) {
            const int idx = tid + i * 256;
            const int r = idx >> 4, c = idx & 15;
            const uint32_t so = (uint32_t)(r * AST + c * 8) * 2;
            const size_t go = head_base + (size_t)(qbase + r) * HDIM + c * 8;
            cp16(sb + so, g_Qh + go);
            cp16(sb + Q_BYTES + so, g_Ql + go);
        }
        {
            const uint32_t kvb = sb + 2 * Q_BYTES;
            #pragma unroll
            for (int i = 0; i < 4; i++) {
                const int idx = tid + i * 256;
                const int r = idx >> 4, c = idx & 15;
                const uint32_t so = (uint32_t)(r * AST + c * 8) * 2;
                const size_t go = head_base + (size_t)r * HDIM + c * 8;
                cp16(kvb + 0 * KV_MAT + so, g_Kh + go);
                cp16(kvb + 1 * KV_MAT + so, g_Kl + go);
                cp16(kvb + 2 * KV_MAT + so, g_Vh + go);
                cp16(kvb + 3 * KV_MAT + so, g_Vl + go);
            }
        }
        CP_COMMIT();

        float o[16][4];
        #pragma unroll
        for (int d = 0; d < 16; d++)
            #pragma unroll
            for (int c = 0; c < 4; c++) o[d][c] = 0.0f;
        float m0 = -1e30f, m1 = -1e30f, l0 = 0.0f, l1 = 0.0f;
        const int wrow = qbase + w * 16;
        const int wqmax = wrow + 15;

        for (int kt = 0; kt < ntiles; kt++) {
            const int st = kt & 1;
            if (kt + 1 < ntiles) {
                const int t1 = (kt + 1) * 64;
                const uint32_t kvb = sb + 2 * Q_BYTES + (uint32_t)(st ^ 1) * KV_STAGE;
                #pragma unroll
                for (int i = 0; i < 4; i++) {
                    const int idx = tid + i * 256;
                    const int r = idx >> 4, c = idx & 15;
                    const uint32_t so = (uint32_t)(r * AST + c * 8) * 2;
                    const size_t go = head_base + (size_t)(t1 + r) * HDIM + c * 8;
                    cp16(kvb + 0 * KV_MAT + so, g_Kh + go);
                    cp16(kvb + 1 * KV_MAT + so, g_Kl + go);
                    cp16(kvb + 2 * KV_MAT + so, g_Vh + go);
                    cp16(kvb + 3 * KV_MAT + so, g_Vl + go);
                }
                CP_COMMIT();
                CP_WAIT(1);
            } else {
                CP_WAIT(0);
            }
            __syncthreads();

            const int t0 = kt * 64;
            if (t0 <= wqmax) {
                const uint32_t kvb = sb + 2 * Q_BYTES + (uint32_t)st * KV_STAGE;

                float s[8][4];
                #pragma unroll
                for (int nt = 0; nt < 8; nt++)
                    #pragma unroll
                    for (int c = 0; c < 4; c++) s[nt][c] = 0.0f;

                #pragma unroll
                for (int ks = 0; ks < 8; ks++) {
                    uint32_t qh[4], ql[4];
                    const uint32_t qa = sb + (uint32_t)(qa_r * AST + ks * 16 + qa_c) * 2;
                    LDSM4(qh, qa);
                    LDSM4(ql, qa + Q_BYTES);
                    #pragma unroll
                    for (int np = 0; np < 4; np++) {
                        uint32_t kh[4], kl[4];
                        const uint32_t ka = kvb
                            + (uint32_t)((kb_r + np * 16) * AST + ks * 16 + kb_c) * 2;
                        LDSM4(kh, ka);
                        LDSM4(kl, ka + KV_MAT);
                        MMA16816(s[2 * np],     qh, &kh[0]);
                        MMA16816(s[2 * np],     qh, &kl[0]);
                        MMA16816(s[2 * np],     ql, &kh[0]);
                        MMA16816(s[2 * np + 1], qh, &kh[2]);
                        MMA16816(s[2 * np + 1], qh, &kl[2]);
                        MMA16816(s[2 * np + 1], ql, &kh[2]);
                    }
                }

                if (t0 + 63 > wrow) {
                    const int r0g = wrow + g, r1g = wrow + g + 8;
                    #pragma unroll
                    for (int nt = 0; nt < 8; nt++) {
                        const int cbase = t0 + nt * 8 + tq * 2;
                        if (cbase     > r0g) s[nt][0] = -1e30f;
                        if (cbase + 1 > r0g) s[nt][1] = -1e30f;
                        if (cbase     > r1g) s[nt][2] = -1e30f;
                        if (cbase + 1 > r1g) s[nt][3] = -1e30f;
                    }
                }

                float rm0 = -1e30f, rm1 = -1e30f;
                #pragma unroll
                for (int nt = 0; nt < 8; nt++) {
                    rm0 = fmaxf(rm0, fmaxf(s[nt][0], s[nt][1]));
                    rm1 = fmaxf(rm1, fmaxf(s[nt][2], s[nt][3]));
                }
                rm0 = fmaxf(rm0, __shfl_xor_sync(0xffffffffu, rm0, 1));
                rm0 = fmaxf(rm0, __shfl_xor_sync(0xffffffffu, rm0, 2));
                rm1 = fmaxf(rm1, __shfl_xor_sync(0xffffffffu, rm1, 1));
                rm1 = fmaxf(rm1, __shfl_xor_sync(0xffffffffu, rm1, 2));
                const float mn0 = fmaxf(m0, rm0);
                const float mn1 = fmaxf(m1, rm1);
                const float c0 = __expf(m0 - mn0);
                const float c1 = __expf(m1 - mn1);
                float sum0 = 0.0f, sum1 = 0.0f;
                #pragma unroll
                for (int nt = 0; nt < 8; nt++) {
                    s[nt][0] = __expf(s[nt][0] - mn0);
                    s[nt][1] = __expf(s[nt][1] - mn0);
                    s[nt][2] = __expf(s[nt][2] - mn1);
                    s[nt][3] = __expf(s[nt][3] - mn1);
                    sum0 += s[nt][0] + s[nt][1];
                    sum1 += s[nt][2] + s[nt][3];
                }
                sum0 += __shfl_xor_sync(0xffffffffu, sum0, 1);
                sum0 += __shfl_xor_sync(0xffffffffu, sum0, 2);
                sum1 += __shfl_xor_sync(0xffffffffu, sum1, 1);
                sum1 += __shfl_xor_sync(0xffffffffu, sum1, 2);
                m0 = mn0; m1 = mn1;
                l0 = l0 * c0 + sum0;
                l1 = l1 * c1 + sum1;
                #pragma unroll
                for (int d = 0; d < 16; d++) {
                    o[d][0] *= c0; o[d][1] *= c0;
                    o[d][2] *= c1; o[d][3] *= c1;
                }

                uint32_t ph[4][4], pl[4][4];
                #pragma unroll
                for (int k2 = 0; k2 < 4; k2++) {
                    ph[k2][0] = bf2pack(s[2 * k2][0],     s[2 * k2][1]);
                    ph[k2][1] = bf2pack(s[2 * k2][2],     s[2 * k2][3]);
                    ph[k2][2] = bf2pack(s[2 * k2 + 1][0], s[2 * k2 + 1][1]);
                    ph[k2][3] = bf2pack(s[2 * k2 + 1][2], s[2 * k2 + 1][3]);
                    pl[k2][0] = bf2pack(bf16res(s[2 * k2][0]),     bf16res(s[2 * k2][1]));
                    pl[k2][1] = bf2pack(bf16res(s[2 * k2][2]),     bf16res(s[2 * k2][3]));
                    pl[k2][2] = bf2pack(bf16res(s[2 * k2 + 1][0]), bf16res(s[2 * k2 + 1][1]));
                    pl[k2][3] = bf2pack(bf16res(s[2 * k2 + 1][2]), bf16res(s[2 * k2 + 1][3]));
                }

                #pragma unroll
                for (int k2 = 0; k2 < 4; k2++) {
                    #pragma unroll
                    for (int dp = 0; dp < 8; dp++) {
                        uint32_t vh[4], vl[4];
                        const uint32_t va = kvb + 2 * KV_MAT
                            + (uint32_t)((k2 * 16 + vt_r) * AST + dp * 16 + vt_c) * 2;
                        LDSM4T(vh, va);
                        LDSM4T(vl, va + KV_MAT);
                        MMA16816(o[2 * dp],     ph[k2], &vh[0]);
                        MMA16816(o[2 * dp],     ph[k2], &vl[0]);
                        MMA16816(o[2 * dp],     pl[k2], &vh[0]);
                        MMA16816(o[2 * dp + 1], ph[k2], &vh[2]);
                        MMA16816(o[2 * dp + 1], ph[k2], &vl[2]);
                        MMA16816(o[2 * dp + 1], pl[k2], &vh[2]);
                    }
                }
            }
            __syncthreads();
        }

        const float inv0 = 1.0f / l0;
        const float inv1 = 1.0f / l1;
        const int r0g = qbase + w * 16 + g;
        const int r1g = r0g + 8;
        const size_t off0 = ((size_t)r0g * BATCH + b) * HIDDEN + h * HDIM + tq * 2;
        const size_t off1 = ((size_t)r1g * BATCH + b) * HIDDEN + h * HDIM + tq * 2;
        #pragma unroll
        for (int d = 0; d < 16; d++) {
            const float a0 = o[d][0] * inv0, a1 = o[d][1] * inv0;
            const float a2 = o[d][2] * inv1, a3 = o[d][3] * inv1;
            *(__nv_bfloat162*)(g_Ahi + off0 + d * 8) = split_hi2(a0, a1);
            *(__nv_bfloat162*)(g_Alo + off0 + d * 8) = split_lo2(a0, a1);
            *(__nv_bfloat162*)(g_Ahi + off1 + d * 8) = split_hi2(a2, a3);
            *(__nv_bfloat162*)(g_Alo + off1 + d * 8) = split_lo2(a2, a3);
        }
        __syncthreads();
    }
}

__global__ void copy_bias_kernel(const float* __restrict__ b, float* __restrict__ o)
{
    const int i = blockIdx.x * blockDim.x + threadIdx.x;
    if (i < HIDDEN) o[i] = b[i];
}

// ---------------------------------------------------------------------------
// Launch
// ---------------------------------------------------------------------------
extern "C" void kernel_launch(void* const* d_in, const int* in_sizes, int n_in,
                              void* d_out, int out_size)
{
    const float* hidden  = (const float*)d_in[0];
    const float* w_qkv   = (const float*)d_in[2];
    const float* b_qkv   = (const float*)d_in[3];
    const float* w_dense = (const float*)d_in[4];
    const float* b_dense = (const float*)d_in[5];
    float* out = (float*)d_out;

    __nv_bfloat16 *Ahi, *Alo, *Bqh, *Bql, *Bdh, *Bdl;
    cudaGetSymbolAddress((void**)&Ahi, g_Ahi);
    cudaGetSymbolAddress((void**)&Alo, g_Alo);
    cudaGetSymbolAddress((void**)&Bqh, g_Bqkv_hi);
    cudaGetSymbolAddress((void**)&Bql, g_Bqkv_lo);
    cudaGetSymbolAddress((void**)&Bdh, g_Bd_hi);
    cudaGetSymbolAddress((void**)&Bdl, g_Bd_lo);

    cudaFuncSetAttribute(gemm_bf16x3_mma_kernel,
                         cudaFuncAttributeMaxDynamicSharedMemorySize, GEMM_SMEM);
    cudaFuncSetAttribute(attn_mma_kernel,
                         cudaFuncAttributeMaxDynamicSharedMemorySize, ATTN_SMEM);

    const int n4_act = (M_ROWS * HIDDEN) / 4;

    // 1. Split hidden + w_qkv
    split_rm_kernel<<<(n4_act + 255) / 256, 256>>>(hidden, Ahi, Alo, n4_act);
    split_tr_kernel<<<dim3(QKV_N / 32, HIDDEN / 32), dim3(32, 8)>>>(
        w_qkv, Bqh, Bql, HIDDEN, QKV_N);

    // 2. QKV projection with fused per-head split epilogue (mode 1)
    gemm_bf16x3_mma_kernel<<<dim3(QKV_N / 256, M_ROWS / 128), 512, GEMM_SMEM>>>(
        Ahi, Alo, Bqh, Bql, b_qkv, nullptr, M_ROWS, QKV_N, HIDDEN, 1);

    // 3. Causal flash attention (writes ctx pre-split into Ahi/Alo)
    attn_mma_kernel<<<dim3(8, 32), 256, ATTN_SMEM>>>();

    // 4. Dense projection (skip_bias_add), fp32 out (mode 0)
    split_tr_kernel<<<dim3(HIDDEN / 32, HIDDEN / 32), dim3(32, 8)>>>(
        w_dense, Bdh, Bdl, HIDDEN, HIDDEN);
    gemm_bf16x3_mma_kernel<<<dim3(HIDDEN / 256, M_ROWS / 128), 512, GEMM_SMEM>>>(
        Ahi, Alo, Bdh, Bdl, nullptr, out, M_ROWS, HIDDEN, HIDDEN, 0);

    // 5. b_dense returned separately -> output tail (if present)
    if (out_size >= M_ROWS * HIDDEN + HIDDEN) {
        copy_bias_kernel<<<(HIDDEN + 255) / 256, 256>>>(
            b_dense, out + (size_t)M_ROWS * HIDDEN);
    }
}

// round 15
// speedup vs baseline: 1.0068x; 1.0068x over previous
#include <cuda_runtime.h>
#include <cuda_bf16.h>
#include <cstdint>

// Problem constants
#define SEQ     2048
#define BATCH   2
#define HIDDEN  2048
#define NHEADS  16
#define HDIM    128
#define M_ROWS  (SEQ * BATCH)       // 4096
#define QKV_N   (3 * HIDDEN)        // 6144

// ---------------------------------------------------------------------------
// Scratch (device globals: allocation-free per harness rules)
// ---------------------------------------------------------------------------
__device__ __nv_bfloat16 g_Ahi[(size_t)M_ROWS * HIDDEN];
__device__ __nv_bfloat16 g_Alo[(size_t)M_ROWS * HIDDEN];
__device__ __nv_bfloat16 g_Bqkv_hi[(size_t)QKV_N * HIDDEN];
__device__ __nv_bfloat16 g_Bqkv_lo[(size_t)QKV_N * HIDDEN];
__device__ __nv_bfloat16 g_Bd_hi[(size_t)HIDDEN * HIDDEN];
__device__ __nv_bfloat16 g_Bd_lo[(size_t)HIDDEN * HIDDEN];
#define HSZ ((size_t)32 * SEQ * HDIM)
__device__ __nv_bfloat16 g_Qh[HSZ];
__device__ __nv_bfloat16 g_Ql[HSZ];
__device__ __nv_bfloat16 g_Kh[HSZ];
__device__ __nv_bfloat16 g_Kl[HSZ];
__device__ __nv_bfloat16 g_Vh[HSZ];
__device__ __nv_bfloat16 g_Vl[HSZ];

// ---------------------------------------------------------------------------
// Helpers
// ---------------------------------------------------------------------------
__device__ __forceinline__ uint32_t smem_to_u32(const void* p) {
    uint32_t a;
    asm("{ .reg .u64 t; cvta.to.shared.u64 t, %1; cvt.u32.u64 %0, t; }" : "=r"(a) : "l"(p));
    return a;
}
__device__ __forceinline__ void cp16(uint32_t s, const void* g) {
    asm volatile("cp.async.cg.shared.global [%0], [%1], 16;" :: "r"(s), "l"(g));
}
#define CP_COMMIT() asm volatile("cp.async.commit_group;" ::: "memory")
#define CP_WAIT(n)  asm volatile("cp.async.wait_group %0;" :: "n"(n) : "memory")

#define MMA16816(d, a, b) \
    asm volatile("mma.sync.aligned.m16n8k16.row.col.f32.bf16.bf16.f32 " \
        "{%0,%1,%2,%3}, {%4,%5,%6,%7}, {%8,%9}, {%0,%1,%2,%3};" \
        : "+f"((d)[0]), "+f"((d)[1]), "+f"((d)[2]), "+f"((d)[3]) \
        : "r"((a)[0]), "r"((a)[1]), "r"((a)[2]), "r"((a)[3]), \
          "r"((b)[0]), "r"((b)[1]))

#define LDSM4(r, addr) \
    asm volatile("ldmatrix.sync.aligned.m8n8.x4.shared.b16 {%0,%1,%2,%3}, [%4];" \
        : "=r"((r)[0]), "=r"((r)[1]), "=r"((r)[2]), "=r"((r)[3]) : "r"(addr))
#define LDSM4T(r, addr) \
    asm volatile("ldmatrix.sync.aligned.m8n8.x4.trans.shared.b16 {%0,%1,%2,%3}, [%4];" \
        : "=r"((r)[0]), "=r"((r)[1]), "=r"((r)[2]), "=r"((r)[3]) : "r"(addr))

__device__ __forceinline__ uint32_t bf2pack(float a, float b) {
    __nv_bfloat162 t = __floats2bfloat162_rn(a, b);
    return *(uint32_t*)&t;
}
__device__ __forceinline__ float bf16res(float x) {
    return x - __bfloat162float(__float2bfloat16(x));
}
__device__ __forceinline__ __nv_bfloat162 split_hi2(float a, float b) {
    return __nv_bfloat162(__float2bfloat16(a), __float2bfloat16(b));
}
__device__ __forceinline__ __nv_bfloat162 split_lo2(float a, float b) {
    return __nv_bfloat162(__float2bfloat16(bf16res(a)), __float2bfloat16(bf16res(b)));
}

// ---------------------------------------------------------------------------
// Conversion kernels
// ---------------------------------------------------------------------------
__global__ void split_rm_kernel(const float* __restrict__ in,
                                __nv_bfloat16* __restrict__ hi,
                                __nv_bfloat16* __restrict__ lo, int n4)
{
    int i = blockIdx.x * blockDim.x + threadIdx.x;
    if (i >= n4) return;
    float4 v = ((const float4*)in)[i];
    ((__nv_bfloat162*)hi)[2 * i]     = split_hi2(v.x, v.y);
    ((__nv_bfloat162*)hi)[2 * i + 1] = split_hi2(v.z, v.w);
    ((__nv_bfloat162*)lo)[2 * i]     = split_lo2(v.x, v.y);
    ((__nv_bfloat162*)lo)[2 * i + 1] = split_lo2(v.z, v.w);
}

__global__ void split_tr_kernel(const float* __restrict__ in,
                                __nv_bfloat16* __restrict__ hi,
                                __nv_bfloat16* __restrict__ lo, int K, int N)
{
    __shared__ float t[32][33];
    const int n0 = blockIdx.x * 32, k0 = blockIdx.y * 32;
    const int tx = threadIdx.x, ty = threadIdx.y;
    #pragma unroll
    for (int i = 0; i < 4; i++)
        t[ty + 8 * i][tx] = in[(size_t)(k0 + ty + 8 * i) * N + n0 + tx];
    __syncthreads();
    #pragma unroll
    for (int i = 0; i < 4; i++) {
        const int r = ty + 8 * i;
        const float x = t[tx][r];
        __nv_bfloat16 h = __float2bfloat16(x);
        __nv_bfloat16 l = __float2bfloat16(x - __bfloat162float(h));
        const size_t o = (size_t)(n0 + r) * K + k0 + tx;
        hi[o] = h; lo[o] = l;
    }
}

// ---------------------------------------------------------------------------
// bf16x3 mma.sync GEMM. CTA tile 128x256, 256 threads = 8 warps (2m x 4n),
// warp tile 64x64 (high MMA:LDSM ratio), BK=32, 3-stage cp.async pipeline,
// 1 CTA/SM. C[M,N] = A[M,K] @ B^T (B stored [N,K]).
// D = AhBh + AhBl + AlBh (fp32 acc).
// out_mode 0: fp32 C (+bias). out_mode 1: QKV split epilogue.
// ---------------------------------------------------------------------------
#define GBK 32
#define LDS_STRIDE 40
#define A_MAT (128 * LDS_STRIDE * 2)          // 10240 B
#define B_MAT (256 * LDS_STRIDE * 2)          // 20480 B
#define OFF_AH 0
#define OFF_AL A_MAT
#define OFF_BH (2 * A_MAT)
#define OFF_BL (2 * A_MAT + B_MAT)
#define STAGE_BYTES (2 * A_MAT + 2 * B_MAT)   // 61440 B
#define NSTAGE 3
#define GEMM_SMEM (NSTAGE * STAGE_BYTES)      // 184320 B, 1 CTA/SM

__global__ __launch_bounds__(256) void gemm_bf16x3_mma_kernel(
    const __nv_bfloat16* __restrict__ Ahi, const __nv_bfloat16* __restrict__ Alo,
    const __nv_bfloat16* __restrict__ Bhi, const __nv_bfloat16* __restrict__ Blo,
    const float* __restrict__ bias, float* __restrict__ C,
    int M, int N, int K, int out_mode)
{
    extern __shared__ char smem[];
    const uint32_t sbase = smem_to_u32(smem);
    const int tid  = threadIdx.x;
    const int wid  = tid >> 5;
    const int lane = tid & 31;
    const int g    = lane >> 2;
    const int tq   = lane & 3;
    const int wm   = wid & 1;            // 2 m-warps * 64 rows
    const int wn   = wid >> 1;           // 4 n-warps * 64 cols
    const int row0 = blockIdx.y * 128;
    const int col0 = blockIdx.x * 256;
    const int NC   = K / GBK;

    const int l_row = tid >> 2;          // 0..63
    const int l_kc  = (tid & 3) * 8;     // element offset within BK

    float acc[4][8][4];
    #pragma unroll
    for (int mt = 0; mt < 4; mt++)
        #pragma unroll
        for (int nt = 0; nt < 8; nt++)
            #pragma unroll
            for (int q = 0; q < 4; q++) acc[mt][nt][q] = 0.0f;

    auto load_stage = [&](int st, int kc) {
        const int kel = kc * GBK;
        const uint32_t stb = sbase + (uint32_t)st * STAGE_BYTES;
        // A: 128 rows (2 sweeps of 64)
        #pragma unroll
        for (int i = 0; i < 2; i++) {
            const int row = l_row + i * 64;
            const uint32_t soff = (uint32_t)(row * LDS_STRIDE + l_kc) * 2;
            const size_t ga = (size_t)(row0 + row) * K + kel + l_kc;
            cp16(stb + OFF_AH + soff, Ahi + ga);
            cp16(stb + OFF_AL + soff, Alo + ga);
        }
        // B: 256 rows (4 sweeps of 64)
        #pragma unroll
        for (int i = 0; i < 4; i++) {
            const int row = l_row + i * 64;
            const uint32_t soff = (uint32_t)(row * LDS_STRIDE + l_kc) * 2;
            const size_t gb = (size_t)(col0 + row) * K + kel + l_kc;
            cp16(stb + OFF_BH + soff, Bhi + gb);
            cp16(stb + OFF_BL + soff, Blo + gb);
        }
        CP_COMMIT();
    };

    load_stage(0, 0);
    load_stage(1, 1);

    const int a_r = wm * 64 + (lane & 15);                       // + mt*16
    const int a_c = (lane >> 4) << 3;
    const int b_r = wn * 64 + (lane & 7) + (((lane >> 4) & 1) << 3);  // + np*16
    const int b_c = ((lane >> 3) & 1) << 3;

    for (int kc = 0; kc < NC; kc++) {
        CP_WAIT(1);
        __syncthreads();
        if (kc + 2 < NC) load_stage((kc + 2) % NSTAGE, kc + 2);
        else             CP_COMMIT();          // uniform group count

        const uint32_t stb = sbase + (uint32_t)(kc % NSTAGE) * STAGE_BYTES;

        #pragma unroll
        for (int ks = 0; ks < GBK; ks += 16) {
            uint32_t ah[4][4], al[4][4];
            #pragma unroll
            for (int mt = 0; mt < 4; mt++) {
                const uint32_t aa = stb + (uint32_t)(((a_r + mt * 16) * LDS_STRIDE) + ks + a_c) * 2;
                LDSM4(ah[mt], aa + OFF_AH);
                LDSM4(al[mt], aa + OFF_AL);
            }
            #pragma unroll
            for (int np = 0; np < 4; np++) {
                uint32_t bh[4], bl[4];
                const uint32_t ba = stb
                    + (uint32_t)(((b_r + np * 16) * LDS_STRIDE) + ks + b_c) * 2;
                LDSM4(bh, ba + OFF_BH);
                LDSM4(bl, ba + OFF_BL);
                #pragma unroll
                for (int half = 0; half < 2; half++) {
                    const int nt = 2 * np + half;
                    #pragma unroll
                    for (int mt = 0; mt < 4; mt++) {
                        MMA16816(acc[mt][nt], ah[mt], &bh[half * 2]);
                        MMA16816(acc[mt][nt], ah[mt], &bl[half * 2]);
                        MMA16816(acc[mt][nt], al[mt], &bh[half * 2]);
                    }
                }
            }
        }
    }

    __syncthreads();

    if (out_mode == 0) {
        #pragma unroll
        for (int mt = 0; mt < 4; mt++) {
            const int r1 = row0 + wm * 64 + mt * 16 + g;
            const int r2 = r1 + 8;
            #pragma unroll
            for (int nt = 0; nt < 8; nt++) {
                const int c = col0 + wn * 64 + nt * 8 + tq * 2;
                float2 o1 = make_float2(acc[mt][nt][0], acc[mt][nt][1]);
                float2 o2 = make_float2(acc[mt][nt][2], acc[mt][nt][3]);
                if (bias) {
                    const float b0 = bias[c], b1 = bias[c + 1];
                    o1.x += b0; o1.y += b1;
                    o2.x += b0; o2.y += b1;
                }
                *(float2*)(C + (size_t)r1 * N + c) = o1;
                *(float2*)(C + (size_t)r2 * N + c) = o2;
            }
        }
    } else {
        const float qs = 0.08838834764831845f;
        #pragma unroll
        for (int mt = 0; mt < 4; mt++) {
            const int r1 = row0 + wm * 64 + mt * 16 + g;
            const int r2 = r1 + 8;
            const int s1 = r1 >> 1, b1 = r1 & 1;
            const int s2 = r2 >> 1, b2 = r2 & 1;
            #pragma unroll
            for (int nt = 0; nt < 8; nt++) {
                const int c = col0 + wn * 64 + nt * 8 + tq * 2;
                const int h = c / 384;
                const int rem = c - h * 384;
                const int m = rem >> 7;
                const int d = rem & 127;
                float v10 = acc[mt][nt][0] + bias[c];
                float v11 = acc[mt][nt][1] + bias[c + 1];
                float v20 = acc[mt][nt][2] + bias[c];
                float v21 = acc[mt][nt][3] + bias[c + 1];
                if (m == 0) { v10 *= qs; v11 *= qs; v20 *= qs; v21 *= qs; }
                __nv_bfloat16* hi = (m == 0) ? g_Qh : (m == 1) ? g_Kh : g_Vh;
                __nv_bfloat16* lo = (m == 0) ? g_Ql : (m == 1) ? g_Kl : g_Vl;
                const size_t o1 = ((size_t)(b1 * 16 + h) * SEQ + s1) * HDIM + d;
                const size_t o2 = ((size_t)(b2 * 16 + h) * SEQ + s2) * HDIM + d;
                *(__nv_bfloat162*)(hi + o1) = split_hi2(v10, v11);
                *(__nv_bfloat162*)(lo + o1) = split_lo2(v10, v11);
                *(__nv_bfloat162*)(hi + o2) = split_hi2(v20, v21);
                *(__nv_bfloat162*)(lo + o2) = split_lo2(v20, v21);
            }
        }
    }
}

// ---------------------------------------------------------------------------
// Flash attention, bf16x3 mma.sync, causal (unchanged from R8 pass).
// ---------------------------------------------------------------------------
#define AST 136
#define Q_BYTES (128 * AST * 2)
#define KV_MAT (64 * AST * 2)
#define KV_STAGE (4 * KV_MAT)
#define ATTN_SMEM (2 * Q_BYTES + 2 * KV_STAGE)

__global__ __launch_bounds__(256) void attn_mma_kernel()
{
    extern __shared__ char smem[];
    const uint32_t sb = smem_to_u32(smem);
    const int tid  = threadIdx.x;
    const int lane = tid & 31;
    const int w    = tid >> 5;
    const int g    = lane >> 2;
    const int tq   = lane & 3;
    const int bh   = blockIdx.y;
    const int b    = bh >> 4;
    const int h    = bh & 15;
    const size_t head_base = (size_t)bh * SEQ * HDIM;

    const int qa_r = w * 16 + (lane & 15);
    const int qa_c = (lane >> 4) << 3;
    const int kb_r = (lane & 7) + (((lane >> 4) & 1) << 3);
    const int kb_c = ((lane >> 3) & 1) << 3;
    const int vt_r = lane & 15;
    const int vt_c = (lane >> 4) << 3;

    for (int pass = 0; pass < 2; pass++) {
        const int qt = pass ? (15 - (int)blockIdx.x) : (int)blockIdx.x;
        const int qbase = qt * 128;
        const int ntiles = 2 * qt + 2;

        #pragma unroll
        for (int i = 0; i < 8; i++) {
            const int idx = tid + i * 256;
            const int r = idx >> 4, c = idx & 15;
            const uint32_t so = (uint32_t)(r * AST + c * 8) * 2;
            const size_t go = head_base + (size_t)(qbase + r) * HDIM + c * 8;
            cp16(sb + so, g_Qh + go);
            cp16(sb + Q_BYTES + so, g_Ql + go);
        }
        {
            const uint32_t kvb = sb + 2 * Q_BYTES;
            #pragma unroll
            for (int i = 0; i < 4; i++) {
                const int idx = tid + i * 256;
                const int r = idx >> 4, c = idx & 15;
                const uint32_t so = (uint32_t)(r * AST + c * 8) * 2;
                const size_t go = head_base + (size_t)r * HDIM + c * 8;
                cp16(kvb + 0 * KV_MAT + so, g_Kh + go);
                cp16(kvb + 1 * KV_MAT + so, g_Kl + go);
                cp16(kvb + 2 * KV_MAT + so, g_Vh + go);
                cp16(kvb + 3 * KV_MAT + so, g_Vl + go);
            }
        }
        CP_COMMIT();

        float o[16][4];
        #pragma unroll
        for (int d = 0; d < 16; d++)
            #pragma unroll
            for (int c = 0; c < 4; c++) o[d][c] = 0.0f;
        float m0 = -1e30f, m1 = -1e30f, l0 = 0.0f, l1 = 0.0f;
        const int wrow = qbase + w * 16;
        const int wqmax = wrow + 15;

        for (int kt = 0; kt < ntiles; kt++) {
            const int st = kt & 1;
            if (kt + 1 < ntiles) {
                const int t1 = (kt + 1) * 64;
                const uint32_t kvb = sb + 2 * Q_BYTES + (uint32_t)(st ^ 1) * KV_STAGE;
                #pragma unroll
                for (int i = 0; i < 4; i++) {
                    const int idx = tid + i * 256;
                    const int r = idx >> 4, c = idx & 15;
                    const uint32_t so = (uint32_t)(r * AST + c * 8) * 2;
                    const size_t go = head_base + (size_t)(t1 + r) * HDIM + c * 8;
                    cp16(kvb + 0 * KV_MAT + so, g_Kh + go);
                    cp16(kvb + 1 * KV_MAT + so, g_Kl + go);
                    cp16(kvb + 2 * KV_MAT + so, g_Vh + go);
                    cp16(kvb + 3 * KV_MAT + so, g_Vl + go);
                }
                CP_COMMIT();
                CP_WAIT(1);
            } else {
                CP_WAIT(0);
            }
            __syncthreads();

            const int t0 = kt * 64;
            if (t0 <= wqmax) {
                const uint32_t kvb = sb + 2 * Q_BYTES + (uint32_t)st * KV_STAGE;

                float s[8][4];
                #pragma unroll
                for (int nt = 0; nt < 8; nt++)
                    #pragma unroll
                    for (int c = 0; c < 4; c++) s[nt][c] = 0.0f;

                #pragma unroll
                for (int ks = 0; ks < 8; ks++) {
                    uint32_t qh[4], ql[4];
                    const uint32_t qa = sb + (uint32_t)(qa_r * AST + ks * 16 + qa_c) * 2;
                    LDSM4(qh, qa);
                    LDSM4(ql, qa + Q_BYTES);
                    #pragma unroll
                    for (int np = 0; np < 4; np++) {
                        uint32_t kh[4], kl[4];
                        const uint32_t ka = kvb
                            + (uint32_t)((kb_r + np * 16) * AST + ks * 16 + kb_c) * 2;
                        LDSM4(kh, ka);
                        LDSM4(kl, ka + KV_MAT);
                        MMA16816(s[2 * np],     qh, &kh[0]);
                        MMA16816(s[2 * np],     qh, &kl[0]);
                        MMA16816(s[2 * np],     ql, &kh[0]);
                        MMA16816(s[2 * np + 1], qh, &kh[2]);
                        MMA16816(s[2 * np + 1], qh, &kl[2]);
                        MMA16816(s[2 * np + 1], ql, &kh[2]);
                    }
                }

                if (t0 + 63 > wrow) {
                    const int r0g = wrow + g, r1g = wrow + g + 8;
                    #pragma unroll
                    for (int nt = 0; nt < 8; nt++) {
                        const int cbase = t0 + nt * 8 + tq * 2;
                        if (cbase     > r0g) s[nt][0] = -1e30f;
                        if (cbase + 1 > r0g) s[nt][1] = -1e30f;
                        if (cbase     > r1g) s[nt][2] = -1e30f;
                        if (cbase + 1 > r1g) s[nt][3] = -1e30f;
                    }
                }

                float rm0 = -1e30f, rm1 = -1e30f;
                #pragma unroll
                for (int nt = 0; nt < 8; nt++) {
                    rm0 = fmaxf(rm0, fmaxf(s[nt][0], s[nt][1]));
                    rm1 = fmaxf(rm1, fmaxf(s[nt][2], s[nt][3]));
                }
                rm0 = fmaxf(rm0, __shfl_xor_sync(0xffffffffu, rm0, 1));
                rm0 = fmaxf(rm0, __shfl_xor_sync(0xffffffffu, rm0, 2));
                rm1 = fmaxf(rm1, __shfl_xor_sync(0xffffffffu, rm1, 1));
                rm1 = fmaxf(rm1, __shfl_xor_sync(0xffffffffu, rm1, 2));
                const float mn0 = fmaxf(m0, rm0);
                const float mn1 = fmaxf(m1, rm1);
                const float c0 = __expf(m0 - mn0);
                const float c1 = __expf(m1 - mn1);
                float sum0 = 0.0f, sum1 = 0.0f;
                #pragma unroll
                for (int nt = 0; nt < 8; nt++) {
                    s[nt][0] = __expf(s[nt][0] - mn0);
                    s[nt][1] = __expf(s[nt][1] - mn0);
                    s[nt][2] = __expf(s[nt][2] - mn1);
                    s[nt][3] = __expf(s[nt][3] - mn1);
                    sum0 += s[nt][0] + s[nt][1];
                    sum1 += s[nt][2] + s[nt][3];
                }
                sum0 += __shfl_xor_sync(0xffffffffu, sum0, 1);
                sum0 += __shfl_xor_sync(0xffffffffu, sum0, 2);
                sum1 += __shfl_xor_sync(0xffffffffu, sum1, 1);
                sum1 += __shfl_xor_sync(0xffffffffu, sum1, 2);
                m0 = mn0; m1 = mn1;
                l0 = l0 * c0 + sum0;
                l1 = l1 * c1 + sum1;
                #pragma unroll
                for (int d = 0; d < 16; d++) {
                    o[d][0] *= c0; o[d][1] *= c0;
                    o[d][2] *= c1; o[d][3] *= c1;
                }

                uint32_t ph[4][4], pl[4][4];
                #pragma unroll
                for (int k2 = 0; k2 < 4; k2++) {
                    ph[k2][0] = bf2pack(s[2 * k2][0],     s[2 * k2][1]);
                    ph[k2][1] = bf2pack(s[2 * k2][2],     s[2 * k2][3]);
                    ph[k2][2] = bf2pack(s[2 * k2 + 1][0], s[2 * k2 + 1][1]);
                    ph[k2][3] = bf2pack(s[2 * k2 + 1][2], s[2 * k2 + 1][3]);
                    pl[k2][0] = bf2pack(bf16res(s[2 * k2][0]),     bf16res(s[2 * k2][1]));
                    pl[k2][1] = bf2pack(bf16res(s[2 * k2][2]),     bf16res(s[2 * k2][3]));
                    pl[k2][2] = bf2pack(bf16res(s[2 * k2 + 1][0]), bf16res(s[2 * k2 + 1][1]));
                    pl[k2][3] = bf2pack(bf16res(s[2 * k2 + 1][2]), bf16res(s[2 * k2 + 1][3]));
                }

                #pragma unroll
                for (int k2 = 0; k2 < 4; k2++) {
                    #pragma unroll
                    for (int dp = 0; dp < 8; dp++) {
                        uint32_t vh[4], vl[4];
                        const uint32_t va = kvb + 2 * KV_MAT
                            + (uint32_t)((k2 * 16 + vt_r) * AST + dp * 16 + vt_c) * 2;
                        LDSM4T(vh, va);
                        LDSM4T(vl, va + KV_MAT);
                        MMA16816(o[2 * dp],     ph[k2], &vh[0]);
                        MMA16816(o[2 * dp],     ph[k2], &vl[0]);
                        MMA16816(o[2 * dp],     pl[k2], &vh[0]);
                        MMA16816(o[2 * dp + 1], ph[k2], &vh[2]);
                        MMA16816(o[2 * dp + 1], ph[k2], &vl[2]);
                        MMA16816(o[2 * dp + 1], pl[k2], &vh[2]);
                    }
                }
            }
            __syncthreads();
        }

        const float inv0 = 1.0f / l0;
        const float inv1 = 1.0f / l1;
        const int r0g = qbase + w * 16 + g;
        const int r1g = r0g + 8;
        const size_t off0 = ((size_t)r0g * BATCH + b) * HIDDEN + h * HDIM + tq * 2;
        const size_t off1 = ((size_t)r1g * BATCH + b) * HIDDEN + h * HDIM + tq * 2;
        #pragma unroll
        for (int d = 0; d < 16; d++) {
            const float a0 = o[d][0] * inv0, a1 = o[d][1] * inv0;
            const float a2 = o[d][2] * inv1, a3 = o[d][3] * inv1;
            *(__nv_bfloat162*)(g_Ahi + off0 + d * 8) = split_hi2(a0, a1);
            *(__nv_bfloat162*)(g_Alo + off0 + d * 8) = split_lo2(a0, a1);
            *(__nv_bfloat162*)(g_Ahi + off1 + d * 8) = split_hi2(a2, a3);
            *(__nv_bfloat162*)(g_Alo + off1 + d * 8) = split_lo2(a2, a3);
        }
        __syncthreads();
    }
}

__global__ void copy_bias_kernel(const float* __restrict__ b, float* __restrict__ o)
{
    const int i = blockIdx.x * blockDim.x + threadIdx.x;
    if (i < HIDDEN) o[i] = b[i];
}

// ---------------------------------------------------------------------------
// Launch
// ---------------------------------------------------------------------------
extern "C" void kernel_launch(void* const* d_in, const int* in_sizes, int n_in,
                              void* d_out, int out_size)
{
    const float* hidden  = (const float*)d_in[0];
    const float* w_qkv   = (const float*)d_in[2];
    const float* b_qkv   = (const float*)d_in[3];
    const float* w_dense = (const float*)d_in[4];
    const float* b_dense = (const float*)d_in[5];
    float* out = (float*)d_out;

    __nv_bfloat16 *Ahi, *Alo, *Bqh, *Bql, *Bdh, *Bdl;
    cudaGetSymbolAddress((void**)&Ahi, g_Ahi);
    cudaGetSymbolAddress((void**)&Alo, g_Alo);
    cudaGetSymbolAddress((void**)&Bqh, g_Bqkv_hi);
    cudaGetSymbolAddress((void**)&Bql, g_Bqkv_lo);
    cudaGetSymbolAddress((void**)&Bdh, g_Bd_hi);
    cudaGetSymbolAddress((void**)&Bdl, g_Bd_lo);

    cudaFuncSetAttribute(gemm_bf16x3_mma_kernel,
                         cudaFuncAttributeMaxDynamicSharedMemorySize, GEMM_SMEM);
    cudaFuncSetAttribute(attn_mma_kernel,
                         cudaFuncAttributeMaxDynamicSharedMemorySize, ATTN_SMEM);

    const int n4_act = (M_ROWS * HIDDEN) / 4;

    // 1. Split hidden + w_qkv
    split_rm_kernel<<<(n4_act + 255) / 256, 256>>>(hidden, Ahi, Alo, n4_act);
    split_tr_kernel<<<dim3(QKV_N / 32, HIDDEN / 32), dim3(32, 8)>>>(
        w_qkv, Bqh, Bql, HIDDEN, QKV_N);

    // 2. QKV projection with fused per-head split epilogue (mode 1)
    gemm_bf16x3_mma_kernel<<<dim3(QKV_N / 256, M_ROWS / 128), 256, GEMM_SMEM>>>(
        Ahi, Alo, Bqh, Bql, b_qkv, nullptr, M_ROWS, QKV_N, HIDDEN, 1);

    // 3. Causal flash attention (writes ctx pre-split into Ahi/Alo)
    attn_mma_kernel<<<dim3(8, 32), 256, ATTN_SMEM>>>();

    // 4. Dense projection (skip_bias_add), fp32 out (mode 0)
    split_tr_kernel<<<dim3(HIDDEN / 32, HIDDEN / 32), dim3(32, 8)>>>(
        w_dense, Bdh, Bdl, HIDDEN, HIDDEN);
    gemm_bf16x3_mma_kernel<<<dim3(HIDDEN / 256, M_ROWS / 128), 256, GEMM_SMEM>>>(
        Ahi, Alo, Bdh, Bdl, nullptr, out, M_ROWS, HIDDEN, HIDDEN, 0);

    // 5. b_dense returned separately -> output tail (if present)
    if (out_size >= M_ROWS * HIDDEN + HIDDEN) {
        copy_bias_kernel<<<(HIDDEN + 255) / 256, 256>>>(
            b_dense, out + (size_t)M_ROWS * HIDDEN);
    }
}

// round 16
// speedup vs baseline: 1.2250x; 1.2167x over previous
#include <cuda_runtime.h>
#include <cuda_bf16.h>
#include <cstdint>

// Problem constants
#define SEQ     2048
#define BATCH   2
#define HIDDEN  2048
#define NHEADS  16
#define HDIM    128
#define M_ROWS  (SEQ * BATCH)       // 4096
#define QKV_N   (3 * HIDDEN)        // 6144

// ---------------------------------------------------------------------------
// Scratch (device globals: allocation-free per harness rules)
// ---------------------------------------------------------------------------
__device__ __nv_bfloat16 g_Ahi[(size_t)M_ROWS * HIDDEN];
__device__ __nv_bfloat16 g_Alo[(size_t)M_ROWS * HIDDEN];
__device__ __nv_bfloat16 g_Bqkv_hi[(size_t)QKV_N * HIDDEN];
__device__ __nv_bfloat16 g_Bqkv_lo[(size_t)QKV_N * HIDDEN];
__device__ __nv_bfloat16 g_Bd_hi[(size_t)HIDDEN * HIDDEN];
__device__ __nv_bfloat16 g_Bd_lo[(size_t)HIDDEN * HIDDEN];
#define HSZ ((size_t)32 * SEQ * HDIM)
__device__ __nv_bfloat16 g_Qh[HSZ];
__device__ __nv_bfloat16 g_Ql[HSZ];
__device__ __nv_bfloat16 g_Kh[HSZ];
__device__ __nv_bfloat16 g_Kl[HSZ];
__device__ __nv_bfloat16 g_Vh[HSZ];
__device__ __nv_bfloat16 g_Vl[HSZ];

// ---------------------------------------------------------------------------
// Helpers
// ---------------------------------------------------------------------------
__device__ __forceinline__ uint32_t smem_to_u32(const void* p) {
    uint32_t a;
    asm("{ .reg .u64 t; cvta.to.shared.u64 t, %1; cvt.u32.u64 %0, t; }" : "=r"(a) : "l"(p));
    return a;
}
__device__ __forceinline__ void cp16(uint32_t s, const void* g) {
    asm volatile("cp.async.cg.shared.global [%0], [%1], 16;" :: "r"(s), "l"(g));
}
#define CP_COMMIT() asm volatile("cp.async.commit_group;" ::: "memory")
#define CP_WAIT(n)  asm volatile("cp.async.wait_group %0;" :: "n"(n) : "memory")

#define MMA16816(d, a, b) \
    asm volatile("mma.sync.aligned.m16n8k16.row.col.f32.bf16.bf16.f32 " \
        "{%0,%1,%2,%3}, {%4,%5,%6,%7}, {%8,%9}, {%0,%1,%2,%3};" \
        : "+f"((d)[0]), "+f"((d)[1]), "+f"((d)[2]), "+f"((d)[3]) \
        : "r"((a)[0]), "r"((a)[1]), "r"((a)[2]), "r"((a)[3]), \
          "r"((b)[0]), "r"((b)[1]))

#define LDSM4(r, addr) \
    asm volatile("ldmatrix.sync.aligned.m8n8.x4.shared.b16 {%0,%1,%2,%3}, [%4];" \
        : "=r"((r)[0]), "=r"((r)[1]), "=r"((r)[2]), "=r"((r)[3]) : "r"(addr))
#define LDSM4T(r, addr) \
    asm volatile("ldmatrix.sync.aligned.m8n8.x4.trans.shared.b16 {%0,%1,%2,%3}, [%4];" \
        : "=r"((r)[0]), "=r"((r)[1]), "=r"((r)[2]), "=r"((r)[3]) : "r"(addr))

__device__ __forceinline__ uint32_t bf2pack(float a, float b) {
    __nv_bfloat162 t = __floats2bfloat162_rn(a, b);
    return *(uint32_t*)&t;
}
__device__ __forceinline__ float bf16res(float x) {
    return x - __bfloat162float(__float2bfloat16(x));
}
__device__ __forceinline__ __nv_bfloat162 split_hi2(float a, float b) {
    return __nv_bfloat162(__float2bfloat16(a), __float2bfloat16(b));
}
__device__ __forceinline__ __nv_bfloat162 split_lo2(float a, float b) {
    return __nv_bfloat162(__float2bfloat16(bf16res(a)), __float2bfloat16(bf16res(b)));
}

// ---------------------------------------------------------------------------
// Conversion kernels
// ---------------------------------------------------------------------------
__global__ void split_rm_kernel(const float* __restrict__ in,
                                __nv_bfloat16* __restrict__ hi,
                                __nv_bfloat16* __restrict__ lo, int n4)
{
    int i = blockIdx.x * blockDim.x + threadIdx.x;
    if (i >= n4) return;
    float4 v = ((const float4*)in)[i];
    ((__nv_bfloat162*)hi)[2 * i]     = split_hi2(v.x, v.y);
    ((__nv_bfloat162*)hi)[2 * i + 1] = split_hi2(v.z, v.w);
    ((__nv_bfloat162*)lo)[2 * i]     = split_lo2(v.x, v.y);
    ((__nv_bfloat162*)lo)[2 * i + 1] = split_lo2(v.z, v.w);
}

__global__ void split_tr_kernel(const float* __restrict__ in,
                                __nv_bfloat16* __restrict__ hi,
                                __nv_bfloat16* __restrict__ lo, int K, int N)
{
    __shared__ float t[32][33];
    const int n0 = blockIdx.x * 32, k0 = blockIdx.y * 32;
    const int tx = threadIdx.x, ty = threadIdx.y;
    #pragma unroll
    for (int i = 0; i < 4; i++)
        t[ty + 8 * i][tx] = in[(size_t)(k0 + ty + 8 * i) * N + n0 + tx];
    __syncthreads();
    #pragma unroll
    for (int i = 0; i < 4; i++) {
        const int r = ty + 8 * i;
        const float x = t[tx][r];
        __nv_bfloat16 h = __float2bfloat16(x);
        __nv_bfloat16 l = __float2bfloat16(x - __bfloat162float(h));
        const size_t o = (size_t)(n0 + r) * K + k0 + tx;
        hi[o] = h; lo[o] = l;
    }
}

// ---------------------------------------------------------------------------
// bf16x3 mma.sync GEMM. CTA 128x128, 256 thr, 8 warps (4m x 2n, warp tile
// 32x64 — R8 geometry), BK=64 per stage with SW128 XOR swizzle (no pad),
// 3-stage cp.async pipeline (192 KB smem, 1 CTA/SM), 32 barriers total,
// 192 MMAs/warp between barriers, prefetch distance 2 chunks.
// C[M,N] = A[M,K] @ B^T (B stored [N,K]); D = AhBh + AhBl + AlBh.
// out_mode 0: fp32 C (+bias). out_mode 1: QKV split epilogue.
// ---------------------------------------------------------------------------
#define GBK 64
#define MAT_BYTES (128 * 128)                  // 128 rows x 64 bf16 = 16384 B
#define OFF_AH 0
#define OFF_AL MAT_BYTES
#define OFF_BH (2 * MAT_BYTES)
#define OFF_BL (3 * MAT_BYTES)
#define STAGE_BYTES (4 * MAT_BYTES)            // 65536 B
#define NSTAGE 3
#define GEMM_SMEM (NSTAGE * STAGE_BYTES)       // 196608 B, 1 CTA/SM

// swizzled byte offset within one matrix: row (0..127), 16B-chunk c (0..7)
#define SWZ_OFF(row, c) ((uint32_t)((row) * 128 + (((c) ^ ((row) & 7)) << 4)))

__global__ __launch_bounds__(256) void gemm_bf16x3_mma_kernel(
    const __nv_bfloat16* __restrict__ Ahi, const __nv_bfloat16* __restrict__ Alo,
    const __nv_bfloat16* __restrict__ Bhi, const __nv_bfloat16* __restrict__ Blo,
    const float* __restrict__ bias, float* __restrict__ C,
    int M, int N, int K, int out_mode)
{
    extern __shared__ char smem[];
    const uint32_t sbase = smem_to_u32(smem);
    const int tid  = threadIdx.x;
    const int wid  = tid >> 5;
    const int lane = tid & 31;
    const int g    = lane >> 2;
    const int tq   = lane & 3;
    const int wm   = wid & 3;            // 4 m-warps * 32 rows
    const int wn   = wid >> 2;           // 2 n-warps * 64 cols
    const int row0 = blockIdx.y * 128;
    const int col0 = blockIdx.x * 128;
    const int NC   = K / GBK;            // 32

    // cp.async mapping: per matrix 1024 16B-chunks; 256 thr x 4
    const int l_row = tid >> 3;          // iterates +32 per i (4 sweeps = 128 rows)
    const int l_c   = tid & 7;           // k chunk 0..7 (8 elem each)

    float acc[2][8][4];
    #pragma unroll
    for (int mt = 0; mt < 2; mt++)
        #pragma unroll
        for (int nt = 0; nt < 8; nt++)
            #pragma unroll
            for (int q = 0; q < 4; q++) acc[mt][nt][q] = 0.0f;

    auto load_stage = [&](int st, int kc) {
        const int kel = kc * GBK;
        const uint32_t stb = sbase + (uint32_t)st * STAGE_BYTES;
        #pragma unroll
        for (int i = 0; i < 4; i++) {
            const int row = l_row + i * 32;
            const uint32_t soff = SWZ_OFF(row, l_c);
            const size_t ga = (size_t)(row0 + row) * K + kel + l_c * 8;
            const size_t gb = (size_t)(col0 + row) * K + kel + l_c * 8;
            cp16(stb + OFF_AH + soff, Ahi + ga);
            cp16(stb + OFF_AL + soff, Alo + ga);
            cp16(stb + OFF_BH + soff, Bhi + gb);
            cp16(stb + OFF_BL + soff, Blo + gb);
        }
        CP_COMMIT();
    };

    load_stage(0, 0);
    load_stage(1, 1);

    // ldmatrix lane components
    const int a_row  = wm * 32 + (lane & 15);          // + mt*16
    const int a_ch   = lane >> 4;                      // 16B half of k16 step
    const int b_row  = wn * 64 + (lane & 7) + (((lane >> 4) & 1) << 3);  // + np*16
    const int b_ch   = (lane >> 3) & 1;

    for (int kc = 0; kc < NC; kc++) {
        CP_WAIT(1);
        __syncthreads();
        if (kc + 2 < NC) load_stage((kc + 2) % NSTAGE, kc + 2);
        else             CP_COMMIT();          // uniform group count

        const uint32_t stb = sbase + (uint32_t)(kc % NSTAGE) * STAGE_BYTES;

        #pragma unroll
        for (int ks = 0; ks < 4; ks++) {       // 4 k16 steps per BK=64 chunk
            uint32_t ah[2][4], al[2][4];
            #pragma unroll
            for (int mt = 0; mt < 2; mt++) {
                const int r = a_row + mt * 16;
                const uint32_t aa = stb + SWZ_OFF(r, 2 * ks + a_ch);
                LDSM4(ah[mt], aa + OFF_AH);
                LDSM4(al[mt], aa + OFF_AL);
            }
            uint32_t bh[4][4], bl[4][4];
            #pragma unroll
            for (int np = 0; np < 4; np++) {
                const int r = b_row + np * 16;
                const uint32_t ba = stb + SWZ_OFF(r, 2 * ks + b_ch);
                LDSM4(bh[np], ba + OFF_BH);
                LDSM4(bl[np], ba + OFF_BL);
            }
            #pragma unroll
            for (int mt = 0; mt < 2; mt++)
                #pragma unroll
                for (int nt = 0; nt < 8; nt++) {
                    uint32_t* bhp = &bh[nt >> 1][(nt & 1) * 2];
                    uint32_t* blp = &bl[nt >> 1][(nt & 1) * 2];
                    MMA16816(acc[mt][nt], ah[mt], bhp);
                    MMA16816(acc[mt][nt], ah[mt], blp);
                    MMA16816(acc[mt][nt], al[mt], bhp);
                }
        }
    }

    __syncthreads();

    if (out_mode == 0) {
        #pragma unroll
        for (int mt = 0; mt < 2; mt++) {
            const int r1 = row0 + wm * 32 + mt * 16 + g;
            const int r2 = r1 + 8;
            #pragma unroll
            for (int nt = 0; nt < 8; nt++) {
                const int c = col0 + wn * 64 + nt * 8 + tq * 2;
                float2 o1 = make_float2(acc[mt][nt][0], acc[mt][nt][1]);
                float2 o2 = make_float2(acc[mt][nt][2], acc[mt][nt][3]);
                if (bias) {
                    const float b0 = bias[c], b1 = bias[c + 1];
                    o1.x += b0; o1.y += b1;
                    o2.x += b0; o2.y += b1;
                }
                *(float2*)(C + (size_t)r1 * N + c) = o1;
                *(float2*)(C + (size_t)r2 * N + c) = o2;
            }
        }
    } else {
        const float qs = 0.08838834764831845f;
        #pragma unroll
        for (int mt = 0; mt < 2; mt++) {
            const int r1 = row0 + wm * 32 + mt * 16 + g;
            const int r2 = r1 + 8;
            const int s1 = r1 >> 1, b1 = r1 & 1;
            const int s2 = r2 >> 1, b2 = r2 & 1;
            #pragma unroll
            for (int nt = 0; nt < 8; nt++) {
                const int c = col0 + wn * 64 + nt * 8 + tq * 2;
                const int h = c / 384;
                const int rem = c - h * 384;
                const int m = rem >> 7;
                const int d = rem & 127;
                float v10 = acc[mt][nt][0] + bias[c];
                float v11 = acc[mt][nt][1] + bias[c + 1];
                float v20 = acc[mt][nt][2] + bias[c];
                float v21 = acc[mt][nt][3] + bias[c + 1];
                if (m == 0) { v10 *= qs; v11 *= qs; v20 *= qs; v21 *= qs; }
                __nv_bfloat16* hi = (m == 0) ? g_Qh : (m == 1) ? g_Kh : g_Vh;
                __nv_bfloat16* lo = (m == 0) ? g_Ql : (m == 1) ? g_Kl : g_Vl;
                const size_t o1 = ((size_t)(b1 * 16 + h) * SEQ + s1) * HDIM + d;
                const size_t o2 = ((size_t)(b2 * 16 + h) * SEQ + s2) * HDIM + d;
                *(__nv_bfloat162*)(hi + o1) = split_hi2(v10, v11);
                *(__nv_bfloat162*)(lo + o1) = split_lo2(v10, v11);
                *(__nv_bfloat162*)(hi + o2) = split_hi2(v20, v21);
                *(__nv_bfloat162*)(lo + o2) = split_lo2(v20, v21);
            }
        }
    }
}

// ---------------------------------------------------------------------------
// Flash attention, bf16x3 mma.sync, causal (unchanged from R8 pass).
// ---------------------------------------------------------------------------
#define AST 136
#define Q_BYTES (128 * AST * 2)
#define KV_MAT (64 * AST * 2)
#define KV_STAGE (4 * KV_MAT)
#define ATTN_SMEM (2 * Q_BYTES + 2 * KV_STAGE)

__global__ __launch_bounds__(256) void attn_mma_kernel()
{
    extern __shared__ char smem[];
    const uint32_t sb = smem_to_u32(smem);
    const int tid  = threadIdx.x;
    const int lane = tid & 31;
    const int w    = tid >> 5;
    const int g    = lane >> 2;
    const int tq   = lane & 3;
    const int bh   = blockIdx.y;
    const int b    = bh >> 4;
    const int h    = bh & 15;
    const size_t head_base = (size_t)bh * SEQ * HDIM;

    const int qa_r = w * 16 + (lane & 15);
    const int qa_c = (lane >> 4) << 3;
    const int kb_r = (lane & 7) + (((lane >> 4) & 1) << 3);
    const int kb_c = ((lane >> 3) & 1) << 3;
    const int vt_r = lane & 15;
    const int vt_c = (lane >> 4) << 3;

    for (int pass = 0; pass < 2; pass++) {
        const int qt = pass ? (15 - (int)blockIdx.x) : (int)blockIdx.x;
        const int qbase = qt * 128;
        const int ntiles = 2 * qt + 2;

        #pragma unroll
        for (int i = 0; i < 8; i++) {
            const int idx = tid + i * 256;
            const int r = idx >> 4, c = idx & 15;
            const uint32_t so = (uint32_t)(r * AST + c * 8) * 2;
            const size_t go = head_base + (size_t)(qbase + r) * HDIM + c * 8;
            cp16(sb + so, g_Qh + go);
            cp16(sb + Q_BYTES + so, g_Ql + go);
        }
        {
            const uint32_t kvb = sb + 2 * Q_BYTES;
            #pragma unroll
            for (int i = 0; i < 4; i++) {
                const int idx = tid + i * 256;
                const int r = idx >> 4, c = idx & 15;
                const uint32_t so = (uint32_t)(r * AST + c * 8) * 2;
                const size_t go = head_base + (size_t)r * HDIM + c * 8;
                cp16(kvb + 0 * KV_MAT + so, g_Kh + go);
                cp16(kvb + 1 * KV_MAT + so, g_Kl + go);
                cp16(kvb + 2 * KV_MAT + so, g_Vh + go);
                cp16(kvb + 3 * KV_MAT + so, g_Vl + go);
            }
        }
        CP_COMMIT();

        float o[16][4];
        #pragma unroll
        for (int d = 0; d < 16; d++)
            #pragma unroll
            for (int c = 0; c < 4; c++) o[d][c] = 0.0f;
        float m0 = -1e30f, m1 = -1e30f, l0 = 0.0f, l1 = 0.0f;
        const int wrow = qbase + w * 16;
        const int wqmax = wrow + 15;

        for (int kt = 0; kt < ntiles; kt++) {
            const int st = kt & 1;
            if (kt + 1 < ntiles) {
                const int t1 = (kt + 1) * 64;
                const uint32_t kvb = sb + 2 * Q_BYTES + (uint32_t)(st ^ 1) * KV_STAGE;
                #pragma unroll
                for (int i = 0; i < 4; i++) {
                    const int idx = tid + i * 256;
                    const int r = idx >> 4, c = idx & 15;
                    const uint32_t so = (uint32_t)(r * AST + c * 8) * 2;
                    const size_t go = head_base + (size_t)(t1 + r) * HDIM + c * 8;
                    cp16(kvb + 0 * KV_MAT + so, g_Kh + go);
                    cp16(kvb + 1 * KV_MAT + so, g_Kl + go);
                    cp16(kvb + 2 * KV_MAT + so, g_Vh + go);
                    cp16(kvb + 3 * KV_MAT + so, g_Vl + go);
                }
                CP_COMMIT();
                CP_WAIT(1);
            } else {
                CP_WAIT(0);
            }
            __syncthreads();

            const int t0 = kt * 64;
            if (t0 <= wqmax) {
                const uint32_t kvb = sb + 2 * Q_BYTES + (uint32_t)st * KV_STAGE;

                float s[8][4];
                #pragma unroll
                for (int nt = 0; nt < 8; nt++)
                    #pragma unroll
                    for (int c = 0; c < 4; c++) s[nt][c] = 0.0f;

                #pragma unroll
                for (int ks = 0; ks < 8; ks++) {
                    uint32_t qh[4], ql[4];
                    const uint32_t qa = sb + (uint32_t)(qa_r * AST + ks * 16 + qa_c) * 2;
                    LDSM4(qh, qa);
                    LDSM4(ql, qa + Q_BYTES);
                    #pragma unroll
                    for (int np = 0; np < 4; np++) {
                        uint32_t kh[4], kl[4];
                        const uint32_t ka = kvb
                            + (uint32_t)((kb_r + np * 16) * AST + ks * 16 + kb_c) * 2;
                        LDSM4(kh, ka);
                        LDSM4(kl, ka + KV_MAT);
                        MMA16816(s[2 * np],     qh, &kh[0]);
                        MMA16816(s[2 * np],     qh, &kl[0]);
                        MMA16816(s[2 * np],     ql, &kh[0]);
                        MMA16816(s[2 * np + 1], qh, &kh[2]);
                        MMA16816(s[2 * np + 1], qh, &kl[2]);
                        MMA16816(s[2 * np + 1], ql, &kh[2]);
                    }
                }

                if (t0 + 63 > wrow) {
                    const int r0g = wrow + g, r1g = wrow + g + 8;
                    #pragma unroll
                    for (int nt = 0; nt < 8; nt++) {
                        const int cbase = t0 + nt * 8 + tq * 2;
                        if (cbase     > r0g) s[nt][0] = -1e30f;
                        if (cbase + 1 > r0g) s[nt][1] = -1e30f;
                        if (cbase     > r1g) s[nt][2] = -1e30f;
                        if (cbase + 1 > r1g) s[nt][3] = -1e30f;
                    }
                }

                float rm0 = -1e30f, rm1 = -1e30f;
                #pragma unroll
                for (int nt = 0; nt < 8; nt++) {
                    rm0 = fmaxf(rm0, fmaxf(s[nt][0], s[nt][1]));
                    rm1 = fmaxf(rm1, fmaxf(s[nt][2], s[nt][3]));
                }
                rm0 = fmaxf(rm0, __shfl_xor_sync(0xffffffffu, rm0, 1));
                rm0 = fmaxf(rm0, __shfl_xor_sync(0xffffffffu, rm0, 2));
                rm1 = fmaxf(rm1, __shfl_xor_sync(0xffffffffu, rm1, 1));
                rm1 = fmaxf(rm1, __shfl_xor_sync(0xffffffffu, rm1, 2));
                const float mn0 = fmaxf(m0, rm0);
                const float mn1 = fmaxf(m1, rm1);
                const float c0 = __expf(m0 - mn0);
                const float c1 = __expf(m1 - mn1);
                float sum0 = 0.0f, sum1 = 0.0f;
                #pragma unroll
                for (int nt = 0; nt < 8; nt++) {
                    s[nt][0] = __expf(s[nt][0] - mn0);
                    s[nt][1] = __expf(s[nt][1] - mn0);
                    s[nt][2] = __expf(s[nt][2] - mn1);
                    s[nt][3] = __expf(s[nt][3] - mn1);
                    sum0 += s[nt][0] + s[nt][1];
                    sum1 += s[nt][2] + s[nt][3];
                }
                sum0 += __shfl_xor_sync(0xffffffffu, sum0, 1);
                sum0 += __shfl_xor_sync(0xffffffffu, sum0, 2);
                sum1 += __shfl_xor_sync(0xffffffffu, sum1, 1);
                sum1 += __shfl_xor_sync(0xffffffffu, sum1, 2);
                m0 = mn0; m1 = mn1;
                l0 = l0 * c0 + sum0;
                l1 = l1 * c1 + sum1;
                #pragma unroll
                for (int d = 0; d < 16; d++) {
                    o[d][0] *= c0; o[d][1] *= c0;
                    o[d][2] *= c1; o[d][3] *= c1;
                }

                uint32_t ph[4][4], pl[4][4];
                #pragma unroll
                for (int k2 = 0; k2 < 4; k2++) {
                    ph[k2][0] = bf2pack(s[2 * k2][0],     s[2 * k2][1]);
                    ph[k2][1] = bf2pack(s[2 * k2][2],     s[2 * k2][3]);
                    ph[k2][2] = bf2pack(s[2 * k2 + 1][0], s[2 * k2 + 1][1]);
                    ph[k2][3] = bf2pack(s[2 * k2 + 1][2], s[2 * k2 + 1][3]);
                    pl[k2][0] = bf2pack(bf16res(s[2 * k2][0]),     bf16res(s[2 * k2][1]));
                    pl[k2][1] = bf2pack(bf16res(s[2 * k2][2]),     bf16res(s[2 * k2][3]));
                    pl[k2][2] = bf2pack(bf16res(s[2 * k2 + 1][0]), bf16res(s[2 * k2 + 1][1]));
                    pl[k2][3] = bf2pack(bf16res(s[2 * k2 + 1][2]), bf16res(s[2 * k2 + 1][3]));
                }

                #pragma unroll
                for (int k2 = 0; k2 < 4; k2++) {
                    #pragma unroll
                    for (int dp = 0; dp < 8; dp++) {
                        uint32_t vh[4], vl[4];
                        const uint32_t va = kvb + 2 * KV_MAT
                            + (uint32_t)((k2 * 16 + vt_r) * AST + dp * 16 + vt_c) * 2;
                        LDSM4T(vh, va);
                        LDSM4T(vl, va + KV_MAT);
                        MMA16816(o[2 * dp],     ph[k2], &vh[0]);
                        MMA16816(o[2 * dp],     ph[k2], &vl[0]);
                        MMA16816(o[2 * dp],     pl[k2], &vh[0]);
                        MMA16816(o[2 * dp + 1], ph[k2], &vh[2]);
                        MMA16816(o[2 * dp + 1], ph[k2], &vl[2]);
                        MMA16816(o[2 * dp + 1], pl[k2], &vh[2]);
                    }
                }
            }
            __syncthreads();
        }

        const float inv0 = 1.0f / l0;
        const float inv1 = 1.0f / l1;
        const int r0g = qbase + w * 16 + g;
        const int r1g = r0g + 8;
        const size_t off0 = ((size_t)r0g * BATCH + b) * HIDDEN + h * HDIM + tq * 2;
        const size_t off1 = ((size_t)r1g * BATCH + b) * HIDDEN + h * HDIM + tq * 2;
        #pragma unroll
        for (int d = 0; d < 16; d++) {
            const float a0 = o[d][0] * inv0, a1 = o[d][1] * inv0;
            const float a2 = o[d][2] * inv1, a3 = o[d][3] * inv1;
            *(__nv_bfloat162*)(g_Ahi + off0 + d * 8) = split_hi2(a0, a1);
            *(__nv_bfloat162*)(g_Alo + off0 + d * 8) = split_lo2(a0, a1);
            *(__nv_bfloat162*)(g_Ahi + off1 + d * 8) = split_hi2(a2, a3);
            *(__nv_bfloat162*)(g_Alo + off1 + d * 8) = split_lo2(a2, a3);
        }
        __syncthreads();
    }
}

__global__ void copy_bias_kernel(const float* __restrict__ b, float* __restrict__ o)
{
    const int i = blockIdx.x * blockDim.x + threadIdx.x;
    if (i < HIDDEN) o[i] = b[i];
}

// ---------------------------------------------------------------------------
// Launch
// ---------------------------------------------------------------------------
extern "C" void kernel_launch(void* const* d_in, const int* in_sizes, int n_in,
                              void* d_out, int out_size)
{
    const float* hidden  = (const float*)d_in[0];
    const float* w_qkv   = (const float*)d_in[2];
    const float* b_qkv   = (const float*)d_in[3];
    const float* w_dense = (const float*)d_in[4];
    const float* b_dense = (const float*)d_in[5];
    float* out = (float*)d_out;

    __nv_bfloat16 *Ahi, *Alo, *Bqh, *Bql, *Bdh, *Bdl;
    cudaGetSymbolAddress((void**)&Ahi, g_Ahi);
    cudaGetSymbolAddress((void**)&Alo, g_Alo);
    cudaGetSymbolAddress((void**)&Bqh, g_Bqkv_hi);
    cudaGetSymbolAddress((void**)&Bql, g_Bqkv_lo);
    cudaGetSymbolAddress((void**)&Bdh, g_Bd_hi);
    cudaGetSymbolAddress((void**)&Bdl, g_Bd_lo);

    cudaFuncSetAttribute(gemm_bf16x3_mma_kernel,
                         cudaFuncAttributeMaxDynamicSharedMemorySize, GEMM_SMEM);
    cudaFuncSetAttribute(attn_mma_kernel,
                         cudaFuncAttributeMaxDynamicSharedMemorySize, ATTN_SMEM);

    const int n4_act = (M_ROWS * HIDDEN) / 4;

    // 1. Split hidden + w_qkv
    split_rm_kernel<<<(n4_act + 255) / 256, 256>>>(hidden, Ahi, Alo, n4_act);
    split_tr_kernel<<<dim3(QKV_N / 32, HIDDEN / 32), dim3(32, 8)>>>(
        w_qkv, Bqh, Bql, HIDDEN, QKV_N);

    // 2. QKV projection with fused per-head split epilogue (mode 1)
    gemm_bf16x3_mma_kernel<<<dim3(QKV_N / 128, M_ROWS / 128), 256, GEMM_SMEM>>>(
        Ahi, Alo, Bqh, Bql, b_qkv, nullptr, M_ROWS, QKV_N, HIDDEN, 1);

    // 3. Causal flash attention (writes ctx pre-split into Ahi/Alo)
    attn_mma_kernel<<<dim3(8, 32), 256, ATTN_SMEM>>>();

    // 4. Dense projection (skip_bias_add), fp32 out (mode 0)
    split_tr_kernel<<<dim3(HIDDEN / 32, HIDDEN / 32), dim3(32, 8)>>>(
        w_dense, Bdh, Bdl, HIDDEN, HIDDEN);
    gemm_bf16x3_mma_kernel<<<dim3(HIDDEN / 128, M_ROWS / 128), 256, GEMM_SMEM>>>(
        Ahi, Alo, Bdh, Bdl, nullptr, out, M_ROWS, HIDDEN, HIDDEN, 0);

    // 5. b_dense returned separately -> output tail (if present)
    if (out_size >= M_ROWS * HIDDEN + HIDDEN) {
        copy_bias_kernel<<<(HIDDEN + 255) / 256, 256>>>(
            b_dense, out + (size_t)M_ROWS * HIDDEN);
    }
}

// round 17
// speedup vs baseline: 1.5883x; 1.2966x over previous
#include <cuda_runtime.h>
#include <cuda_bf16.h>
#include <cuda_fp16.h>
#include <cstdint>

// Problem constants
#define SEQ     2048
#define BATCH   2
#define HIDDEN  2048
#define NHEADS  16
#define HDIM    128
#define M_ROWS  (SEQ * BATCH)       // 4096
#define QKV_N   (3 * HIDDEN)        // 6144

// ---------------------------------------------------------------------------
// Scratch (device globals: allocation-free per harness rules)
// ---------------------------------------------------------------------------
// GEMM activations: fp16 hi/lo split
__device__ __half g_Ahi[(size_t)M_ROWS * HIDDEN];
__device__ __half g_Alo[(size_t)M_ROWS * HIDDEN];
// GEMM weights: single fp16 (transposed)
__device__ __half g_Bqkv[(size_t)QKV_N * HIDDEN];
__device__ __half g_Bd[(size_t)HIDDEN * HIDDEN];
// attention per-head split arrays (bf16x3 path, unchanged): [bh][s][d]
#define HSZ ((size_t)32 * SEQ * HDIM)
__device__ __nv_bfloat16 g_Qh[HSZ];
__device__ __nv_bfloat16 g_Ql[HSZ];
__device__ __nv_bfloat16 g_Kh[HSZ];
__device__ __nv_bfloat16 g_Kl[HSZ];
__device__ __nv_bfloat16 g_Vh[HSZ];
__device__ __nv_bfloat16 g_Vl[HSZ];

// ---------------------------------------------------------------------------
// Helpers
// ---------------------------------------------------------------------------
__device__ __forceinline__ uint32_t smem_to_u32(const void* p) {
    uint32_t a;
    asm("{ .reg .u64 t; cvta.to.shared.u64 t, %1; cvt.u32.u64 %0, t; }" : "=r"(a) : "l"(p));
    return a;
}
__device__ __forceinline__ void cp16(uint32_t s, const void* g) {
    asm volatile("cp.async.cg.shared.global [%0], [%1], 16;" :: "r"(s), "l"(g));
}
#define CP_COMMIT() asm volatile("cp.async.commit_group;" ::: "memory")
#define CP_WAIT(n)  asm volatile("cp.async.wait_group %0;" :: "n"(n) : "memory")

// bf16 mma (attention path)
#define MMA16816(d, a, b) \
    asm volatile("mma.sync.aligned.m16n8k16.row.col.f32.bf16.bf16.f32 " \
        "{%0,%1,%2,%3}, {%4,%5,%6,%7}, {%8,%9}, {%0,%1,%2,%3};" \
        : "+f"((d)[0]), "+f"((d)[1]), "+f"((d)[2]), "+f"((d)[3]) \
        : "r"((a)[0]), "r"((a)[1]), "r"((a)[2]), "r"((a)[3]), \
          "r"((b)[0]), "r"((b)[1]))
// fp16 mma (GEMM path)
#define MMA16816H(d, a, b) \
    asm volatile("mma.sync.aligned.m16n8k16.row.col.f32.f16.f16.f32 " \
        "{%0,%1,%2,%3}, {%4,%5,%6,%7}, {%8,%9}, {%0,%1,%2,%3};" \
        : "+f"((d)[0]), "+f"((d)[1]), "+f"((d)[2]), "+f"((d)[3]) \
        : "r"((a)[0]), "r"((a)[1]), "r"((a)[2]), "r"((a)[3]), \
          "r"((b)[0]), "r"((b)[1]))

#define LDSM4(r, addr) \
    asm volatile("ldmatrix.sync.aligned.m8n8.x4.shared.b16 {%0,%1,%2,%3}, [%4];" \
        : "=r"((r)[0]), "=r"((r)[1]), "=r"((r)[2]), "=r"((r)[3]) : "r"(addr))
#define LDSM4T(r, addr) \
    asm volatile("ldmatrix.sync.aligned.m8n8.x4.trans.shared.b16 {%0,%1,%2,%3}, [%4];" \
        : "=r"((r)[0]), "=r"((r)[1]), "=r"((r)[2]), "=r"((r)[3]) : "r"(addr))

__device__ __forceinline__ uint32_t bf2pack(float a, float b) {
    __nv_bfloat162 t = __floats2bfloat162_rn(a, b);
    return *(uint32_t*)&t;
}
__device__ __forceinline__ float bf16res(float x) {
    return x - __bfloat162float(__float2bfloat16(x));
}
__device__ __forceinline__ __nv_bfloat162 split_hi2(float a, float b) {
    return __nv_bfloat162(__float2bfloat16(a), __float2bfloat16(b));
}
__device__ __forceinline__ __nv_bfloat162 split_lo2(float a, float b) {
    return __nv_bfloat162(__float2bfloat16(bf16res(a)), __float2bfloat16(bf16res(b)));
}
// fp16 split helpers
__device__ __forceinline__ float hres(float x) {
    return x - __half2float(__float2half_rn(x));
}
__device__ __forceinline__ __half2 hsplit_hi2(float a, float b) {
    return __floats2half2_rn(a, b);
}
__device__ __forceinline__ __half2 hsplit_lo2(float a, float b) {
    return __floats2half2_rn(hres(a), hres(b));
}

// ---------------------------------------------------------------------------
// Conversion kernels
// ---------------------------------------------------------------------------
// fp32 row-major -> fp16 hi/lo pair
__global__ void split_rm_half_kernel(const float* __restrict__ in,
                                     __half* __restrict__ hi,
                                     __half* __restrict__ lo, int n4)
{
    int i = blockIdx.x * blockDim.x + threadIdx.x;
    if (i >= n4) return;
    float4 v = ((const float4*)in)[i];
    ((__half2*)hi)[2 * i]     = hsplit_hi2(v.x, v.y);
    ((__half2*)hi)[2 * i + 1] = hsplit_hi2(v.z, v.w);
    ((__half2*)lo)[2 * i]     = hsplit_lo2(v.x, v.y);
    ((__half2*)lo)[2 * i + 1] = hsplit_lo2(v.z, v.w);
}

// fp32 [K,N] -> single fp16 [N,K] (transposed)
__global__ void tr_half_kernel(const float* __restrict__ in,
                               __half* __restrict__ out, int K, int N)
{
    __shared__ float t[32][33];
    const int n0 = blockIdx.x * 32, k0 = blockIdx.y * 32;
    const int tx = threadIdx.x, ty = threadIdx.y;
    #pragma unroll
    for (int i = 0; i < 4; i++)
        t[ty + 8 * i][tx] = in[(size_t)(k0 + ty + 8 * i) * N + n0 + tx];
    __syncthreads();
    #pragma unroll
    for (int i = 0; i < 4; i++) {
        const int r = ty + 8 * i;
        out[(size_t)(n0 + r) * K + k0 + tx] = __float2half_rn(t[tx][r]);
    }
}

// ---------------------------------------------------------------------------
// fp16x2 mma.sync GEMM. CTA 128x128, 256 thr, 8 warps (4m x 2n, warp 32x64),
// BK=64 per stage, SW128 XOR swizzle, 4-stage cp.async pipeline (192 KB,
// 1 CTA/SM), prefetch distance 3. D = Ah*Bh + Al*Bh (A fp16-pair, B fp16).
// C[M,N] = A[M,K] @ B^T (B stored [N,K]).
// out_mode 0: fp32 C (+bias). out_mode 1: QKV bf16-split epilogue.
// ---------------------------------------------------------------------------
#define GBK 64
#define MAT_BYTES (128 * 128)                  // 16384 B
#define OFF_AH 0
#define OFF_AL MAT_BYTES
#define OFF_BH (2 * MAT_BYTES)
#define STAGE_BYTES (3 * MAT_BYTES)            // 49152 B
#define NSTAGE 4
#define GEMM_SMEM (NSTAGE * STAGE_BYTES)       // 196608 B, 1 CTA/SM

#define SWZ_OFF(row, c) ((uint32_t)((row) * 128 + (((c) ^ ((row) & 7)) << 4)))

__global__ __launch_bounds__(256) void gemm_fp16x2_mma_kernel(
    const __half* __restrict__ Ahi, const __half* __restrict__ Alo,
    const __half* __restrict__ Bh16,
    const float* __restrict__ bias, float* __restrict__ C,
    int M, int N, int K, int out_mode)
{
    extern __shared__ char smem[];
    const uint32_t sbase = smem_to_u32(smem);
    const int tid  = threadIdx.x;
    const int wid  = tid >> 5;
    const int lane = tid & 31;
    const int g    = lane >> 2;
    const int tq   = lane & 3;
    const int wm   = wid & 3;            // 4 m-warps * 32 rows
    const int wn   = wid >> 2;           // 2 n-warps * 64 cols
    const int row0 = blockIdx.y * 128;
    const int col0 = blockIdx.x * 128;
    const int NC   = K / GBK;            // 32

    const int l_row = tid >> 3;          // +32 per sweep
    const int l_c   = tid & 7;

    float acc[2][8][4];
    #pragma unroll
    for (int mt = 0; mt < 2; mt++)
        #pragma unroll
        for (int nt = 0; nt < 8; nt++)
            #pragma unroll
            for (int q = 0; q < 4; q++) acc[mt][nt][q] = 0.0f;

    auto load_stage = [&](int st, int kc) {
        const int kel = kc * GBK;
        const uint32_t stb = sbase + (uint32_t)st * STAGE_BYTES;
        #pragma unroll
        for (int i = 0; i < 4; i++) {
            const int row = l_row + i * 32;
            const uint32_t soff = SWZ_OFF(row, l_c);
            const size_t ga = (size_t)(row0 + row) * K + kel + l_c * 8;
            const size_t gb = (size_t)(col0 + row) * K + kel + l_c * 8;
            cp16(stb + OFF_AH + soff, Ahi + ga);
            cp16(stb + OFF_AL + soff, Alo + ga);
            cp16(stb + OFF_BH + soff, Bh16 + gb);
        }
        CP_COMMIT();
    };

    load_stage(0, 0);
    load_stage(1, 1);
    load_stage(2, 2);

    const int a_row = wm * 32 + (lane & 15);
    const int a_ch  = lane >> 4;
    const int b_row = wn * 64 + (lane & 7) + (((lane >> 4) & 1) << 3);
    const int b_ch  = (lane >> 3) & 1;

    for (int kc = 0; kc < NC; kc++) {
        CP_WAIT(2);
        __syncthreads();
        if (kc + 3 < NC) load_stage((kc + 3) % NSTAGE, kc + 3);
        else             CP_COMMIT();          // uniform group count

        const uint32_t stb = sbase + (uint32_t)(kc % NSTAGE) * STAGE_BYTES;

        #pragma unroll
        for (int ks = 0; ks < 4; ks++) {       // 4 k16 steps per BK=64 chunk
            uint32_t ah[2][4], al[2][4];
            #pragma unroll
            for (int mt = 0; mt < 2; mt++) {
                const int r = a_row + mt * 16;
                const uint32_t aa = stb + SWZ_OFF(r, 2 * ks + a_ch);
                LDSM4(ah[mt], aa + OFF_AH);
                LDSM4(al[mt], aa + OFF_AL);
            }
            uint32_t bh[4][4];
            #pragma unroll
            for (int np = 0; np < 4; np++) {
                const int r = b_row + np * 16;
                const uint32_t ba = stb + SWZ_OFF(r, 2 * ks + b_ch);
                LDSM4(bh[np], ba + OFF_BH);
            }
            #pragma unroll
            for (int mt = 0; mt < 2; mt++)
                #pragma unroll
                for (int nt = 0; nt < 8; nt++) {
                    uint32_t* bhp = &bh[nt >> 1][(nt & 1) * 2];
                    MMA16816H(acc[mt][nt], ah[mt], bhp);
                    MMA16816H(acc[mt][nt], al[mt], bhp);
                }
        }
    }

    __syncthreads();

    if (out_mode == 0) {
        #pragma unroll
        for (int mt = 0; mt < 2; mt++) {
            const int r1 = row0 + wm * 32 + mt * 16 + g;
            const int r2 = r1 + 8;
            #pragma unroll
            for (int nt = 0; nt < 8; nt++) {
                const int c = col0 + wn * 64 + nt * 8 + tq * 2;
                float2 o1 = make_float2(acc[mt][nt][0], acc[mt][nt][1]);
                float2 o2 = make_float2(acc[mt][nt][2], acc[mt][nt][3]);
                if (bias) {
                    const float b0 = bias[c], b1 = bias[c + 1];
                    o1.x += b0; o1.y += b1;
                    o2.x += b0; o2.y += b1;
                }
                *(float2*)(C + (size_t)r1 * N + c) = o1;
                *(float2*)(C + (size_t)r2 * N + c) = o2;
            }
        }
    } else {
        // QKV fused epilogue: bias add, Q pre-scale, bf16 hi/lo split,
        // write per-head arrays [bh][s][d] (attention inputs stay bf16x3).
        const float qs = 0.08838834764831845f;
        #pragma unroll
        for (int mt = 0; mt < 2; mt++) {
            const int r1 = row0 + wm * 32 + mt * 16 + g;
            const int r2 = r1 + 8;
            const int s1 = r1 >> 1, b1 = r1 & 1;
            const int s2 = r2 >> 1, b2 = r2 & 1;
            #pragma unroll
            for (int nt = 0; nt < 8; nt++) {
                const int c = col0 + wn * 64 + nt * 8 + tq * 2;
                const int h = c / 384;
                const int rem = c - h * 384;
                const int m = rem >> 7;
                const int d = rem & 127;
                float v10 = acc[mt][nt][0] + bias[c];
                float v11 = acc[mt][nt][1] + bias[c + 1];
                float v20 = acc[mt][nt][2] + bias[c];
                float v21 = acc[mt][nt][3] + bias[c + 1];
                if (m == 0) { v10 *= qs; v11 *= qs; v20 *= qs; v21 *= qs; }
                __nv_bfloat16* hi = (m == 0) ? g_Qh : (m == 1) ? g_Kh : g_Vh;
                __nv_bfloat16* lo = (m == 0) ? g_Ql : (m == 1) ? g_Kl : g_Vl;
                const size_t o1 = ((size_t)(b1 * 16 + h) * SEQ + s1) * HDIM + d;
                const size_t o2 = ((size_t)(b2 * 16 + h) * SEQ + s2) * HDIM + d;
                *(__nv_bfloat162*)(hi + o1) = split_hi2(v10, v11);
                *(__nv_bfloat162*)(lo + o1) = split_lo2(v10, v11);
                *(__nv_bfloat162*)(hi + o2) = split_hi2(v20, v21);
                *(__nv_bfloat162*)(lo + o2) = split_lo2(v20, v21);
            }
        }
    }
}

// ---------------------------------------------------------------------------
// Flash attention, bf16x3 mma.sync, causal. Output epilogue now writes
// fp16 hi/lo into g_Ahi/g_Alo (dense GEMM inputs).
// ---------------------------------------------------------------------------
#define AST 136
#define Q_BYTES (128 * AST * 2)
#define KV_MAT (64 * AST * 2)
#define KV_STAGE (4 * KV_MAT)
#define ATTN_SMEM (2 * Q_BYTES + 2 * KV_STAGE)

__global__ __launch_bounds__(256) void attn_mma_kernel()
{
    extern __shared__ char smem[];
    const uint32_t sb = smem_to_u32(smem);
    const int tid  = threadIdx.x;
    const int lane = tid & 31;
    const int w    = tid >> 5;
    const int g    = lane >> 2;
    const int tq   = lane & 3;
    const int bh   = blockIdx.y;
    const int b    = bh >> 4;
    const int h    = bh & 15;
    const size_t head_base = (size_t)bh * SEQ * HDIM;

    const int qa_r = w * 16 + (lane & 15);
    const int qa_c = (lane >> 4) << 3;
    const int kb_r = (lane & 7) + (((lane >> 4) & 1) << 3);
    const int kb_c = ((lane >> 3) & 1) << 3;
    const int vt_r = lane & 15;
    const int vt_c = (lane >> 4) << 3;

    for (int pass = 0; pass < 2; pass++) {
        const int qt = pass ? (15 - (int)blockIdx.x) : (int)blockIdx.x;
        const int qbase = qt * 128;
        const int ntiles = 2 * qt + 2;

        #pragma unroll
        for (int i = 0; i < 8; i++) {
            const int idx = tid + i * 256;
            const int r = idx >> 4, c = idx & 15;
            const uint32_t so = (uint32_t)(r * AST + c * 8) * 2;
            const size_t go = head_base + (size_t)(qbase + r) * HDIM + c * 8;
            cp16(sb + so, g_Qh + go);
            cp16(sb + Q_BYTES + so, g_Ql + go);
        }
        {
            const uint32_t kvb = sb + 2 * Q_BYTES;
            #pragma unroll
            for (int i = 0; i < 4; i++) {
                const int idx = tid + i * 256;
                const int r = idx >> 4, c = idx & 15;
                const uint32_t so = (uint32_t)(r * AST + c * 8) * 2;
                const size_t go = head_base + (size_t)r * HDIM + c * 8;
                cp16(kvb + 0 * KV_MAT + so, g_Kh + go);
                cp16(kvb + 1 * KV_MAT + so, g_Kl + go);
                cp16(kvb + 2 * KV_MAT + so, g_Vh + go);
                cp16(kvb + 3 * KV_MAT + so, g_Vl + go);
            }
        }
        CP_COMMIT();

        float o[16][4];
        #pragma unroll
        for (int d = 0; d < 16; d++)
            #pragma unroll
            for (int c = 0; c < 4; c++) o[d][c] = 0.0f;
        float m0 = -1e30f, m1 = -1e30f, l0 = 0.0f, l1 = 0.0f;
        const int wrow = qbase + w * 16;
        const int wqmax = wrow + 15;

        for (int kt = 0; kt < ntiles; kt++) {
            const int st = kt & 1;
            if (kt + 1 < ntiles) {
                const int t1 = (kt + 1) * 64;
                const uint32_t kvb = sb + 2 * Q_BYTES + (uint32_t)(st ^ 1) * KV_STAGE;
                #pragma unroll
                for (int i = 0; i < 4; i++) {
                    const int idx = tid + i * 256;
                    const int r = idx >> 4, c = idx & 15;
                    const uint32_t so = (uint32_t)(r * AST + c * 8) * 2;
                    const size_t go = head_base + (size_t)(t1 + r) * HDIM + c * 8;
                    cp16(kvb + 0 * KV_MAT + so, g_Kh + go);
                    cp16(kvb + 1 * KV_MAT + so, g_Kl + go);
                    cp16(kvb + 2 * KV_MAT + so, g_Vh + go);
                    cp16(kvb + 3 * KV_MAT + so, g_Vl + go);
                }
                CP_COMMIT();
                CP_WAIT(1);
            } else {
                CP_WAIT(0);
            }
            __syncthreads();

            const int t0 = kt * 64;
            if (t0 <= wqmax) {
                const uint32_t kvb = sb + 2 * Q_BYTES + (uint32_t)st * KV_STAGE;

                float s[8][4];
                #pragma unroll
                for (int nt = 0; nt < 8; nt++)
                    #pragma unroll
                    for (int c = 0; c < 4; c++) s[nt][c] = 0.0f;

                #pragma unroll
                for (int ks = 0; ks < 8; ks++) {
                    uint32_t qh[4], ql[4];
                    const uint32_t qa = sb + (uint32_t)(qa_r * AST + ks * 16 + qa_c) * 2;
                    LDSM4(qh, qa);
                    LDSM4(ql, qa + Q_BYTES);
                    #pragma unroll
                    for (int np = 0; np < 4; np++) {
                        uint32_t kh[4], kl[4];
                        const uint32_t ka = kvb
                            + (uint32_t)((kb_r + np * 16) * AST + ks * 16 + kb_c) * 2;
                        LDSM4(kh, ka);
                        LDSM4(kl, ka + KV_MAT);
                        MMA16816(s[2 * np],     qh, &kh[0]);
                        MMA16816(s[2 * np],     qh, &kl[0]);
                        MMA16816(s[2 * np],     ql, &kh[0]);
                        MMA16816(s[2 * np + 1], qh, &kh[2]);
                        MMA16816(s[2 * np + 1], qh, &kl[2]);
                        MMA16816(s[2 * np + 1], ql, &kh[2]);
                    }
                }

                if (t0 + 63 > wrow) {
                    const int r0g = wrow + g, r1g = wrow + g + 8;
                    #pragma unroll
                    for (int nt = 0; nt < 8; nt++) {
                        const int cbase = t0 + nt * 8 + tq * 2;
                        if (cbase     > r0g) s[nt][0] = -1e30f;
                        if (cbase + 1 > r0g) s[nt][1] = -1e30f;
                        if (cbase     > r1g) s[nt][2] = -1e30f;
                        if (cbase + 1 > r1g) s[nt][3] = -1e30f;
                    }
                }

                float rm0 = -1e30f, rm1 = -1e30f;
                #pragma unroll
                for (int nt = 0; nt < 8; nt++) {
                    rm0 = fmaxf(rm0, fmaxf(s[nt][0], s[nt][1]));
                    rm1 = fmaxf(rm1, fmaxf(s[nt][2], s[nt][3]));
                }
                rm0 = fmaxf(rm0, __shfl_xor_sync(0xffffffffu, rm0, 1));
                rm0 = fmaxf(rm0, __shfl_xor_sync(0xffffffffu, rm0, 2));
                rm1 = fmaxf(rm1, __shfl_xor_sync(0xffffffffu, rm1, 1));
                rm1 = fmaxf(rm1, __shfl_xor_sync(0xffffffffu, rm1, 2));
                const float mn0 = fmaxf(m0, rm0);
                const float mn1 = fmaxf(m1, rm1);
                const float c0 = __expf(m0 - mn0);
                const float c1 = __expf(m1 - mn1);
                float sum0 = 0.0f, sum1 = 0.0f;
                #pragma unroll
                for (int nt = 0; nt < 8; nt++) {
                    s[nt][0] = __expf(s[nt][0] - mn0);
                    s[nt][1] = __expf(s[nt][1] - mn0);
                    s[nt][2] = __expf(s[nt][2] - mn1);
                    s[nt][3] = __expf(s[nt][3] - mn1);
                    sum0 += s[nt][0] + s[nt][1];
                    sum1 += s[nt][2] + s[nt][3];
                }
                sum0 += __shfl_xor_sync(0xffffffffu, sum0, 1);
                sum0 += __shfl_xor_sync(0xffffffffu, sum0, 2);
                sum1 += __shfl_xor_sync(0xffffffffu, sum1, 1);
                sum1 += __shfl_xor_sync(0xffffffffu, sum1, 2);
                m0 = mn0; m1 = mn1;
                l0 = l0 * c0 + sum0;
                l1 = l1 * c1 + sum1;
                #pragma unroll
                for (int d = 0; d < 16; d++) {
                    o[d][0] *= c0; o[d][1] *= c0;
                    o[d][2] *= c1; o[d][3] *= c1;
                }

                uint32_t ph[4][4], pl[4][4];
                #pragma unroll
                for (int k2 = 0; k2 < 4; k2++) {
                    ph[k2][0] = bf2pack(s[2 * k2][0],     s[2 * k2][1]);
                    ph[k2][1] = bf2pack(s[2 * k2][2],     s[2 * k2][3]);
                    ph[k2][2] = bf2pack(s[2 * k2 + 1][0], s[2 * k2 + 1][1]);
                    ph[k2][3] = bf2pack(s[2 * k2 + 1][2], s[2 * k2 + 1][3]);
                    pl[k2][0] = bf2pack(bf16res(s[2 * k2][0]),     bf16res(s[2 * k2][1]));
                    pl[k2][1] = bf2pack(bf16res(s[2 * k2][2]),     bf16res(s[2 * k2][3]));
                    pl[k2][2] = bf2pack(bf16res(s[2 * k2 + 1][0]), bf16res(s[2 * k2 + 1][1]));
                    pl[k2][3] = bf2pack(bf16res(s[2 * k2 + 1][2]), bf16res(s[2 * k2 + 1][3]));
                }

                #pragma unroll
                for (int k2 = 0; k2 < 4; k2++) {
                    #pragma unroll
                    for (int dp = 0; dp < 8; dp++) {
                        uint32_t vh[4], vl[4];
                        const uint32_t va = kvb + 2 * KV_MAT
                            + (uint32_t)((k2 * 16 + vt_r) * AST + dp * 16 + vt_c) * 2;
                        LDSM4T(vh, va);
                        LDSM4T(vl, va + KV_MAT);
                        MMA16816(o[2 * dp],     ph[k2], &vh[0]);
                        MMA16816(o[2 * dp],     ph[k2], &vl[0]);
                        MMA16816(o[2 * dp],     pl[k2], &vh[0]);
                        MMA16816(o[2 * dp + 1], ph[k2], &vh[2]);
                        MMA16816(o[2 * dp + 1], ph[k2], &vl[2]);
                        MMA16816(o[2 * dp + 1], pl[k2], &vh[2]);
                    }
                }
            }
            __syncthreads();
        }

        // normalize + write ctx pre-split (fp16 hi/lo) for the dense GEMM
        const float inv0 = 1.0f / l0;
        const float inv1 = 1.0f / l1;
        const int r0g = qbase + w * 16 + g;
        const int r1g = r0g + 8;
        const size_t off0 = ((size_t)r0g * BATCH + b) * HIDDEN + h * HDIM + tq * 2;
        const size_t off1 = ((size_t)r1g * BATCH + b) * HIDDEN + h * HDIM + tq * 2;
        #pragma unroll
        for (int d = 0; d < 16; d++) {
            const float a0 = o[d][0] * inv0, a1 = o[d][1] * inv0;
            const float a2 = o[d][2] * inv1, a3 = o[d][3] * inv1;
            *(__half2*)(g_Ahi + off0 + d * 8) = hsplit_hi2(a0, a1);
            *(__half2*)(g_Alo + off0 + d * 8) = hsplit_lo2(a0, a1);
            *(__half2*)(g_Ahi + off1 + d * 8) = hsplit_hi2(a2, a3);
            *(__half2*)(g_Alo + off1 + d * 8) = hsplit_lo2(a2, a3);
        }
        __syncthreads();
    }
}

__global__ void copy_bias_kernel(const float* __restrict__ b, float* __restrict__ o)
{
    const int i = blockIdx.x * blockDim.x + threadIdx.x;
    if (i < HIDDEN) o[i] = b[i];
}

// ---------------------------------------------------------------------------
// Launch
// ---------------------------------------------------------------------------
extern "C" void kernel_launch(void* const* d_in, const int* in_sizes, int n_in,
                              void* d_out, int out_size)
{
    const float* hidden  = (const float*)d_in[0];
    const float* w_qkv   = (const float*)d_in[2];
    const float* b_qkv   = (const float*)d_in[3];
    const float* w_dense = (const float*)d_in[4];
    const float* b_dense = (const float*)d_in[5];
    float* out = (float*)d_out;

    __half *Ahi, *Alo, *Bq, *Bd;
    cudaGetSymbolAddress((void**)&Ahi, g_Ahi);
    cudaGetSymbolAddress((void**)&Alo, g_Alo);
    cudaGetSymbolAddress((void**)&Bq,  g_Bqkv);
    cudaGetSymbolAddress((void**)&Bd,  g_Bd);

    cudaFuncSetAttribute(gemm_fp16x2_mma_kernel,
                         cudaFuncAttributeMaxDynamicSharedMemorySize, GEMM_SMEM);
    cudaFuncSetAttribute(attn_mma_kernel,
                         cudaFuncAttributeMaxDynamicSharedMemorySize, ATTN_SMEM);

    const int n4_act = (M_ROWS * HIDDEN) / 4;

    // 1. Split hidden (fp16 hi/lo) + convert w_qkv (fp16, transposed)
    split_rm_half_kernel<<<(n4_act + 255) / 256, 256>>>(hidden, Ahi, Alo, n4_act);
    tr_half_kernel<<<dim3(QKV_N / 32, HIDDEN / 32), dim3(32, 8)>>>(
        w_qkv, Bq, HIDDEN, QKV_N);

    // 2. QKV projection (fp16x2) with fused per-head bf16-split epilogue
    gemm_fp16x2_mma_kernel<<<dim3(QKV_N / 128, M_ROWS / 128), 256, GEMM_SMEM>>>(
        Ahi, Alo, Bq, b_qkv, nullptr, M_ROWS, QKV_N, HIDDEN, 1);

    // 3. Causal flash attention (bf16x3; writes ctx fp16-split into Ahi/Alo)
    attn_mma_kernel<<<dim3(8, 32), 256, ATTN_SMEM>>>();

    // 4. Dense projection (fp16x2, skip_bias_add), fp32 out
    tr_half_kernel<<<dim3(HIDDEN / 32, HIDDEN / 32), dim3(32, 8)>>>(
        w_dense, Bd, HIDDEN, HIDDEN);
    gemm_fp16x2_mma_kernel<<<dim3(HIDDEN / 128, M_ROWS / 128), 256, GEMM_SMEM>>>(
        Ahi, Alo, Bd, nullptr, out, M_ROWS, HIDDEN, HIDDEN, 0);

    // 5. b_dense returned separately -> output tail (if present)
    if (out_size >= M_ROWS * HIDDEN + HIDDEN) {
        copy_bias_kernel<<<(HIDDEN + 255) / 256, 256>>>(
            b_dense, out + (size_t)M_ROWS * HIDDEN);
    }
}